// round 14
// baseline (speedup 1.0000x reference)
#include <cuda_runtime.h>
#include <cuda_fp16.h>
#include <math.h>
#include <stdint.h>

#define B_AG 32768
#define DID  512
#define HID  1024
#define NOPT 8
#define NACT 16

#define MT    64
#define NTILE 128
#define KCH   32
#define NCH   (DID/KCH)
#define NT    128

#define TAU 4e-3f
#define FIXA_CAP 4096
#define FIXB_CAP 512

// ---- smem byte layout (R7) ----
#define A_HI 0
#define A_LO 5120
#define B_HI 10240
#define B_LO 20480
#define STAGE_BYTES 30720
#define ST_OFF(s)  (1024 + (s)*STAGE_BYTES)
#define HST_OFFB 1024
#define HSTS 133
#define FIN_OFFB 35072
#define FINS 20
#define HWS  20
#define HW_OFFB   62464
#define BIAS_OFFB 72704
#define MISC_OFFB 73216
#define SMEM_BYTES 73984

__device__ int    g_opt_cnt[NOPT];
__device__ int    g_opt_list[NOPT*B_AG];
__device__ int    g_meta_act[B_AG];
__device__ int    g_term_dec[B_AG];
__device__ int    g_fixA_cnt;
__device__ int    g_fixA_list[FIXA_CAP];
__device__ int    g_fixB_cnt[NOPT];
__device__ int    g_fixB_list[NOPT*FIXB_CAP];
__device__ __half g_obsHi[(size_t)B_AG*DID];
__device__ __half g_obsLo[(size_t)B_AG*DID];
__device__ __half g_wHiT[(size_t)10*HID*DID];   // K-major: [mat][h][k]
__device__ __half g_wLoT[(size_t)10*HID*DID];

// ---------------------------------------------------------------------------
__device__ __forceinline__ void cp16(uint32_t dst, const void* src) {
    asm volatile("cp.async.cg.shared.global [%0], [%1], 16;" :: "r"(dst), "l"(src));
}
#define CP_COMMIT() asm volatile("cp.async.commit_group;")

__device__ __forceinline__ void ldm4(uint32_t a, uint32_t r[4]) {
    asm volatile("ldmatrix.sync.aligned.m8n8.x4.shared.b16 {%0,%1,%2,%3}, [%4];"
        : "=r"(r[0]), "=r"(r[1]), "=r"(r[2]), "=r"(r[3]) : "r"(a));
}
__device__ __forceinline__ void mma16816(float d[4], const uint32_t a[4],
                                         uint32_t b0, uint32_t b1) {
    asm volatile("mma.sync.aligned.m16n8k16.row.col.f32.f16.f16.f32 "
        "{%0,%1,%2,%3}, {%4,%5,%6,%7}, {%8,%9}, {%0,%1,%2,%3};"
        : "+f"(d[0]), "+f"(d[1]), "+f"(d[2]), "+f"(d[3])
        : "r"(a[0]), "r"(a[1]), "r"(a[2]), "r"(a[3]), "r"(b0), "r"(b1));
}

// ---------------------------------------------------------------------------
__global__ void __launch_bounds__(256)
convert_obs_kernel(const float* __restrict__ obs) {
    size_t i = ((size_t)blockIdx.x*256 + threadIdx.x)*8;
    float v[8]; __half hi[8], lo[8];
    #pragma unroll
    for (int k = 0; k < 8; ++k) v[k] = obs[i + k];
    #pragma unroll
    for (int k = 0; k < 8; ++k) {
        hi[k] = __float2half_rn(v[k]);
        lo[k] = __float2half_rn(v[k] - __half2float(hi[k]));
    }
    *(uint4*)&g_obsHi[i] = *(uint4*)hi;
    *(uint4*)&g_obsLo[i] = *(uint4*)lo;
    if (blockIdx.x == 0 && threadIdx.x < NOPT) {
        g_opt_cnt[threadIdx.x] = 0;
        g_fixB_cnt[threadIdx.x] = 0;
        if (threadIdx.x == 0) g_fixA_cnt = 0;
    }
}

__global__ void __launch_bounds__(256)
convert_w_kernel(const float* __restrict__ Wm1,
                 const float* __restrict__ Wt1,
                 const float* __restrict__ W1) {
    __shared__ float tile[32][33];
    const int m = blockIdx.z;
    const float* src = (m == 0) ? Wm1 : (m == 1) ? Wt1 : W1 + (size_t)(m-2)*DID*HID;
    const int h0 = blockIdx.x * 32;
    const int k0 = blockIdx.y * 32;
    const int tx = threadIdx.x, ty0 = threadIdx.y;
    #pragma unroll
    for (int r = 0; r < 32; r += 8)
        tile[r + ty0][tx] = src[(size_t)(k0 + r + ty0)*HID + h0 + tx];
    __syncthreads();
    __half* dHi = g_wHiT + (size_t)m*HID*DID;
    __half* dLo = g_wLoT + (size_t)m*HID*DID;
    #pragma unroll
    for (int r = 0; r < 32; r += 8) {
        float x = tile[tx][r + ty0];
        __half hi = __float2half_rn(x);
        __half lo = __float2half_rn(x - __half2float(hi));
        size_t o = (size_t)(h0 + r + ty0)*DID + k0 + tx;
        dHi[o] = hi; dLo[o] = lo;
    }
}

// ---------------------------------------------------------------------------
// 3-pass GEMM tile (exact; identical to R7 gemm_tile)
// ---------------------------------------------------------------------------
__device__ __forceinline__ void gemm3(uint32_t su, int t,
    const __half* aHi0, const __half* aHi1,
    const __half* aLo0, const __half* aLo1,
    const __half* bHi,  const __half* bLo,
    float acc[2][8][4])
{
    const int lane = t & 31, w = t >> 5;
    const int wm = (w & 1) * 32, wn = (w >> 1) * 64;
    const uint32_t drow = (uint32_t)((t >> 2)*80 + (t & 3)*16);

    #define FILL3(s, kc) do {                                   \
        uint32_t _b = su + ST_OFF(s) + drow;                    \
        const int _ko = (kc)*KCH;                               \
        cp16(_b + A_HI,        aHi0 + _ko);                     \
        cp16(_b + A_HI + 2560, aHi1 + _ko);                     \
        cp16(_b + A_LO,        aLo0 + _ko);                     \
        cp16(_b + A_LO + 2560, aLo1 + _ko);                     \
        _Pragma("unroll")                                       \
        for (int _i = 0; _i < 4; ++_i) {                        \
            cp16(_b + B_HI + _i*2560, bHi + _i*32*DID + _ko);   \
            cp16(_b + B_LO + _i*2560, bLo + _i*32*DID + _ko);   \
        }                                                       \
        CP_COMMIT();                                            \
    } while (0)

    FILL3(0, 0);

    #pragma unroll 1
    for (int kc = 0; kc < NCH; ++kc) {
        const int cur = kc & 1;
        if (kc + 1 < NCH) {
            FILL3(cur ^ 1, kc + 1);
            asm volatile("cp.async.wait_group 1;");
        } else {
            asm volatile("cp.async.wait_group 0;");
        }
        __syncthreads();

        const uint32_t sb = su + ST_OFF(cur);
        #pragma unroll
        for (int ks = 0; ks < 2; ++ks) {
            const uint32_t ko = ks*32 + (lane >> 4)*16;
            const uint32_t aadr = sb + A_HI + (uint32_t)((wm + (lane & 15))*80) + ko;
            uint32_t ah0[4], ah1[4], al0[4], al1[4];
            ldm4(aadr,          ah0);
            ldm4(aadr + 16*80,  ah1);
            ldm4(aadr + 5120,         al0);
            ldm4(aadr + 5120 + 16*80, al1);
            uint32_t bh[4][4], bl[4][4];
            #pragma unroll
            for (int j = 0; j < 4; ++j) {
                const uint32_t badr = sb + B_HI
                    + (uint32_t)((wn + j*16 + (lane & 15))*80) + ko;
                ldm4(badr,         bh[j]);
                ldm4(badr + 10240, bl[j]);
            }
            #pragma unroll
            for (int j = 0; j < 4; ++j) {
                mma16816(acc[0][2*j  ], ah0, bh[j][0], bh[j][2]);
                mma16816(acc[0][2*j+1], ah0, bh[j][1], bh[j][3]);
                mma16816(acc[1][2*j  ], ah1, bh[j][0], bh[j][2]);
                mma16816(acc[1][2*j+1], ah1, bh[j][1], bh[j][3]);
            }
            #pragma unroll
            for (int j = 0; j < 4; ++j) {
                mma16816(acc[0][2*j  ], ah0, bl[j][0], bl[j][2]);
                mma16816(acc[0][2*j+1], ah0, bl[j][1], bl[j][3]);
                mma16816(acc[1][2*j  ], ah1, bl[j][0], bl[j][2]);
                mma16816(acc[1][2*j+1], ah1, bl[j][1], bl[j][3]);
            }
            #pragma unroll
            for (int j = 0; j < 4; ++j) {
                mma16816(acc[0][2*j  ], al0, bh[j][0], bh[j][2]);
                mma16816(acc[0][2*j+1], al0, bh[j][1], bh[j][3]);
                mma16816(acc[1][2*j  ], al1, bh[j][0], bh[j][2]);
                mma16816(acc[1][2*j+1], al1, bh[j][1], bh[j][3]);
            }
        }
        __syncthreads();
    }
    #undef FILL3
}

// ---------------------------------------------------------------------------
// 1-pass GEMM tile (hi*hi only)
// ---------------------------------------------------------------------------
__device__ __forceinline__ void gemm1(uint32_t su, int t,
    const __half* aHi0, const __half* aHi1,
    const __half* bHi,
    float acc[2][8][4])
{
    const int lane = t & 31, w = t >> 5;
    const int wm = (w & 1) * 32, wn = (w >> 1) * 64;
    const uint32_t drow = (uint32_t)((t >> 2)*80 + (t & 3)*16);

    #define FILL1(s, kc) do {                                   \
        uint32_t _b = su + ST_OFF(s) + drow;                    \
        const int _ko = (kc)*KCH;                               \
        cp16(_b + A_HI,        aHi0 + _ko);                     \
        cp16(_b + A_HI + 2560, aHi1 + _ko);                     \
        _Pragma("unroll")                                       \
        for (int _i = 0; _i < 4; ++_i)                          \
            cp16(_b + B_HI + _i*2560, bHi + _i*32*DID + _ko);   \
        CP_COMMIT();                                            \
    } while (0)

    FILL1(0, 0);

    #pragma unroll 1
    for (int kc = 0; kc < NCH; ++kc) {
        const int cur = kc & 1;
        if (kc + 1 < NCH) {
            FILL1(cur ^ 1, kc + 1);
            asm volatile("cp.async.wait_group 1;");
        } else {
            asm volatile("cp.async.wait_group 0;");
        }
        __syncthreads();

        const uint32_t sb = su + ST_OFF(cur);
        #pragma unroll
        for (int ks = 0; ks < 2; ++ks) {
            const uint32_t ko = ks*32 + (lane >> 4)*16;
            const uint32_t aadr = sb + A_HI + (uint32_t)((wm + (lane & 15))*80) + ko;
            uint32_t ah0[4], ah1[4];
            ldm4(aadr,          ah0);
            ldm4(aadr + 16*80,  ah1);
            uint32_t bh[4][4];
            #pragma unroll
            for (int j = 0; j < 4; ++j) {
                const uint32_t badr = sb + B_HI
                    + (uint32_t)((wn + j*16 + (lane & 15))*80) + ko;
                ldm4(badr, bh[j]);
            }
            #pragma unroll
            for (int j = 0; j < 4; ++j) {
                mma16816(acc[0][2*j  ], ah0, bh[j][0], bh[j][2]);
                mma16816(acc[0][2*j+1], ah0, bh[j][1], bh[j][3]);
                mma16816(acc[1][2*j  ], ah1, bh[j][0], bh[j][2]);
                mma16816(acc[1][2*j+1], ah1, bh[j][1], bh[j][3]);
            }
        }
        __syncthreads();
    }
    #undef FILL1
}

// relu(acc + bias) -> h staging
__device__ __forceinline__ void stage_h(float* smf, const float acc[2][8][4],
                                        int t) {
    const int lane = t & 31, w = t >> 5;
    const int wm = (w & 1) * 32, wn = (w >> 1) * 64;
    float* hst = smf + HST_OFFB/4;
    const float* bias_s = smf + BIAS_OFFB/4;
    #pragma unroll
    for (int im = 0; im < 2; ++im) {
        #pragma unroll
        for (int j = 0; j < 8; ++j) {
            #pragma unroll
            for (int e = 0; e < 4; ++e) {
                int row = wm + im*16 + (lane >> 2) + (e >> 1)*8;
                int col = wn + j*8 + 2*(lane & 3) + (e & 1);
                float h = acc[im][j][e] + bias_s[col];
                hst[row*HSTS + col] = fmaxf(h, 0.f);
            }
        }
    }
}

#define ZERO_ACC8(acc) do {                                \
    _Pragma("unroll") for (int _i = 0; _i < 2; ++_i)       \
    _Pragma("unroll") for (int _j = 0; _j < 8; ++_j)       \
    _Pragma("unroll") for (int _e = 0; _e < 4; ++_e)       \
        (acc)[_i][_j][_e] = 0.f;                           \
} while (0)

// load phaseA head weights + bias for (net, hbase); caller syncs
__device__ __forceinline__ void loadA_heads(float* smf, int t, int net, int hbase,
    const float* bm1, const float* Wm_pi, const float* Wm_v, const float* Wt2)
{
    float* hw     = smf + HW_OFFB/4;
    float* bias_s = smf + BIAS_OFFB/4;
    if (net == 0) {
        const float* wp = Wm_pi + (size_t)(hbase + t)*NOPT;
        #pragma unroll
        for (int o = 0; o < NOPT; ++o) hw[t*HWS + o] = wp[o];
        hw[t*HWS + 8] = Wm_v[hbase + t];
        bias_s[t] = bm1[hbase + t];
    } else {
        const float* wp = Wt2 + (size_t)(hbase + t)*NOPT;
        #pragma unroll
        for (int o = 0; o < NOPT; ++o) hw[t*HWS + o] = wp[o];
        bias_s[t] = 0.f;
    }
}

// phaseA head contraction for one staged tile
__device__ __forceinline__ void headA_accum(const float* smf, int t, int net,
                                            float accM[9], float accT[8]) {
    const float* hst = smf + HST_OFFB/4;
    const float* hw  = smf + HW_OFFB/4;
    const int r = t & 63, cbase = (t >> 6)*64;
    if (net == 0) {
        #pragma unroll 4
        for (int c = 0; c < 64; ++c) {
            float h = hst[r*HSTS + cbase + c];
            const float* hwc = hw + (cbase + c)*HWS;
            float4 w0 = *(const float4*)(hwc);
            float4 w1 = *(const float4*)(hwc + 4);
            accM[0] += h*w0.x; accM[1] += h*w0.y;
            accM[2] += h*w0.z; accM[3] += h*w0.w;
            accM[4] += h*w1.x; accM[5] += h*w1.y;
            accM[6] += h*w1.z; accM[7] += h*w1.w;
            accM[8] += h*hwc[8];
        }
    } else {
        #pragma unroll 4
        for (int c = 0; c < 64; ++c) {
            float h = hst[r*HSTS + cbase + c];
            const float* hwc = hw + (cbase + c)*HWS;
            float4 w0 = *(const float4*)(hwc);
            float4 w1 = *(const float4*)(hwc + 4);
            accT[0] += h*w0.x; accT[1] += h*w0.y;
            accT[2] += h*w0.z; accT[3] += h*w0.w;
            accT[4] += h*w1.x; accT[5] += h*w1.y;
            accT[6] += h*w1.z; accT[7] += h*w1.w;
        }
    }
}

// phaseA decision + output write for agent g given totals
__device__ __forceinline__ void finishA(int g, const float tot[17],
    const int* dones, const int* exec_opt, float* out, bool allow_flag)
{
    float m = tot[0], m2 = -1e30f; int am = 0;
    #pragma unroll
    for (int o = 1; o < 8; ++o) {
        if (tot[o] > m) { m2 = m; m = tot[o]; am = o; }
        else if (tot[o] > m2) m2 = tot[o];
    }
    float s = 0.f;
    #pragma unroll
    for (int o = 0; o < 8; ++o) s += expf(tot[o] - m);
    float lp = -logf(s);
    int eo = exec_opt[g];
    float tl = tot[9 + eo];
    float tp = 1.0f/(1.0f + expf(-tl));
    bool dn = (dones[g] != 0);
    bool term = dn || (tp > 0.5f);
    out[3*B_AG + g] = (float)am;
    out[4*B_AG + g] = tot[8];
    out[5*B_AG + g] = lp;
    out[6*B_AG + g] = tp;
    g_meta_act[g] = am;
    g_term_dec[g] = term ? 1 : 0;
    if (allow_flag) {
        bool f = ((m - m2) < TAU) || (!dn && (fabsf(tl) < TAU));
        if (f) {
            int p = atomicAdd(&g_fixA_cnt, 1);
            if (p < FIXA_CAP) g_fixA_list[p] = g;
        }
    }
}

// ---------------------------------------------------------------------------
// Phase A fast: 1-pass, writes meta outputs + decision staging + flags.
// ---------------------------------------------------------------------------
__global__ void __launch_bounds__(NT, 2)
phaseA_fast(const int*   __restrict__ dones,
            const int*   __restrict__ exec_opt,
            const float* __restrict__ bm1,
            const float* __restrict__ Wm_pi,
            const float* __restrict__ Wm_v,
            const float* __restrict__ Wt2,
            float* __restrict__ out)
{
    extern __shared__ float smf[];
    const uint32_t su = (uint32_t)__cvta_generic_to_shared(smf);
    const int t = threadIdx.x;
    const int g0 = blockIdx.x * MT;
    float* fin = smf + FIN_OFFB/4;

    const size_t arow = (size_t)(g0 + (t >> 2))*DID + (t & 3)*8;
    const __half* aHi0 = g_obsHi + arow;
    const __half* aHi1 = aHi0 + (size_t)32*DID;

    float accM[9], accT[8];
    #pragma unroll
    for (int k = 0; k < 9; ++k) accM[k] = 0.f;
    #pragma unroll
    for (int k = 0; k < 8; ++k) accT[k] = 0.f;
    const int r = t & 63;

    #pragma unroll 1
    for (int net = 0; net < 2; ++net) {
        #pragma unroll 1
        for (int ht = 0; ht < HID/NTILE; ++ht) {
            const int hbase = ht * NTILE;
            loadA_heads(smf, t, net, hbase, bm1, Wm_pi, Wm_v, Wt2);
            const size_t brow = ((size_t)net*HID + hbase + (t >> 2))*DID + (t & 3)*8;
            float acc[2][8][4];
            ZERO_ACC8(acc);
            gemm1(su, t, aHi0, aHi1, g_wHiT + brow, acc);
            stage_h(smf, acc, t);
            __syncthreads();
            headA_accum(smf, t, net, accM, accT);
            __syncthreads();
        }
    }

    if (t >= 64) {
        #pragma unroll
        for (int k = 0; k < 9; ++k) fin[r*FINS + k] = accM[k];
        #pragma unroll
        for (int k = 0; k < 8; ++k) fin[r*FINS + 9 + k] = accT[k];
    }
    __syncthreads();

    if (t < MT) {
        float tot[17];
        #pragma unroll
        for (int k = 0; k < 9; ++k) tot[k] = accM[k] + fin[t*FINS + k];
        #pragma unroll
        for (int k = 0; k < 8; ++k) tot[9 + k] = accT[k] + fin[t*FINS + 9 + k];
        finishA(g0 + t, tot, dones, exec_opt, out, true);
    }
}

// ---------------------------------------------------------------------------
// Phase A fix: 3-pass exact recompute on flagged agents (gathered).
// ---------------------------------------------------------------------------
__global__ void __launch_bounds__(NT, 2)
phaseA_fix(const int*   __restrict__ dones,
           const int*   __restrict__ exec_opt,
           const float* __restrict__ bm1,
           const float* __restrict__ Wm_pi,
           const float* __restrict__ Wm_v,
           const float* __restrict__ Wt2,
           float* __restrict__ out)
{
    const int cnt = min(g_fixA_cnt, FIXA_CAP);
    const int start = blockIdx.x * MT;
    if (start >= cnt) return;
    const int nvalid = min(MT, cnt - start);

    extern __shared__ float smf[];
    const uint32_t su = (uint32_t)__cvta_generic_to_shared(smf);
    const int t = threadIdx.x;
    float* fin = smf + FIN_OFFB/4;
    int* idx_s = (int*)(smf + MISC_OFFB/4);

    if (t < MT) idx_s[t] = g_fixA_list[start + ((t < nvalid) ? t : 0)];
    __syncthreads();

    const size_t arow0 = (size_t)idx_s[t >> 2]*DID + (t & 3)*8;
    const size_t arow1 = (size_t)idx_s[(t >> 2) + 32]*DID + (t & 3)*8;
    const __half* aHi0 = g_obsHi + arow0;
    const __half* aHi1 = g_obsHi + arow1;
    const __half* aLo0 = g_obsLo + arow0;
    const __half* aLo1 = g_obsLo + arow1;

    float accM[9], accT[8];
    #pragma unroll
    for (int k = 0; k < 9; ++k) accM[k] = 0.f;
    #pragma unroll
    for (int k = 0; k < 8; ++k) accT[k] = 0.f;
    const int r = t & 63;

    #pragma unroll 1
    for (int net = 0; net < 2; ++net) {
        #pragma unroll 1
        for (int ht = 0; ht < HID/NTILE; ++ht) {
            const int hbase = ht * NTILE;
            loadA_heads(smf, t, net, hbase, bm1, Wm_pi, Wm_v, Wt2);
            const size_t brow = ((size_t)net*HID + hbase + (t >> 2))*DID + (t & 3)*8;
            float acc[2][8][4];
            ZERO_ACC8(acc);
            gemm3(su, t, aHi0, aHi1, aLo0, aLo1,
                  g_wHiT + brow, g_wLoT + brow, acc);
            stage_h(smf, acc, t);
            __syncthreads();
            headA_accum(smf, t, net, accM, accT);
            __syncthreads();
        }
    }

    if (t >= 64) {
        #pragma unroll
        for (int k = 0; k < 9; ++k) fin[r*FINS + k] = accM[k];
        #pragma unroll
        for (int k = 0; k < 8; ++k) fin[r*FINS + 9 + k] = accT[k];
    }
    __syncthreads();

    if (t < nvalid) {
        float tot[17];
        #pragma unroll
        for (int k = 0; k < 9; ++k) tot[k] = accM[k] + fin[t*FINS + k];
        #pragma unroll
        for (int k = 0; k < 8; ++k) tot[9 + k] = accT[k] + fin[t*FINS + 9 + k];
        finishA(idx_s[t], tot, dones, exec_opt, out, false);
    }
}

// ---------------------------------------------------------------------------
__global__ void __launch_bounds__(128)
compact_kernel(const int* __restrict__ exec_opt) {
    __shared__ int s_cnt[NOPT], s_base[NOPT];
    const int t = threadIdx.x;
    const int g = blockIdx.x*128 + t;
    if (t < NOPT) s_cnt[t] = 0;
    __syncthreads();
    const int myno = g_term_dec[g] ? g_meta_act[g] : exec_opt[g];
    const int pos = atomicAdd(&s_cnt[myno], 1);
    __syncthreads();
    if (t < NOPT) s_base[t] = atomicAdd(&g_opt_cnt[t], s_cnt[t]);
    __syncthreads();
    g_opt_list[myno*B_AG + s_base[myno] + pos] = g;
}

// ---------------------------------------------------------------------------
// Phase B shared pieces
// ---------------------------------------------------------------------------
__device__ __forceinline__ void loadB_heads(float* smf, int t, int hbase,
    const float* bg, const float* wpig, const float* wvg)
{
    float* hw     = smf + HW_OFFB/4;
    float* bias_s = smf + BIAS_OFFB/4;
    const float* wp = wpig + (size_t)(hbase + t)*NACT;
    #pragma unroll
    for (int a = 0; a < NACT; ++a) hw[t*HWS + a] = wp[a];
    hw[t*HWS + 16] = wvg[hbase + t];
    bias_s[t] = bg[hbase + t];
}

__device__ __forceinline__ void headB_accum(const float* smf, int t,
                                            float accB[17]) {
    const float* hst = smf + HST_OFFB/4;
    const float* hw  = smf + HW_OFFB/4;
    const int r = t & 63, cbase = (t >> 6)*64;
    #pragma unroll 2
    for (int c = 0; c < 64; ++c) {
        float h = hst[r*HSTS + cbase + c];
        const float* hwc = hw + (cbase + c)*HWS;
        float4 w0 = *(const float4*)(hwc);
        float4 w1 = *(const float4*)(hwc + 4);
        float4 w2 = *(const float4*)(hwc + 8);
        float4 w3 = *(const float4*)(hwc + 12);
        accB[0]  += h*w0.x; accB[1]  += h*w0.y;
        accB[2]  += h*w0.z; accB[3]  += h*w0.w;
        accB[4]  += h*w1.x; accB[5]  += h*w1.y;
        accB[6]  += h*w1.z; accB[7]  += h*w1.w;
        accB[8]  += h*w2.x; accB[9]  += h*w2.y;
        accB[10] += h*w2.z; accB[11] += h*w2.w;
        accB[12] += h*w3.x; accB[13] += h*w3.y;
        accB[14] += h*w3.z; accB[15] += h*w3.w;
        accB[16] += h*hwc[16];
    }
}

__device__ __forceinline__ void finishB(int g, int opt, const float lg17[17],
                                        float* out, bool allow_flag) {
    float m = lg17[0], m2 = -1e30f; int am = 0;
    #pragma unroll
    for (int a = 1; a < NACT; ++a) {
        if (lg17[a] > m) { m2 = m; m = lg17[a]; am = a; }
        else if (lg17[a] > m2) m2 = lg17[a];
    }
    float s = 0.f;
    #pragma unroll
    for (int a = 0; a < NACT; ++a) s += expf(lg17[a] - m);
    float lp = -logf(s);
    out[          g] = (float)am;
    out[  B_AG +  g] = lg17[16];
    out[2*B_AG +  g] = lp;
    if (allow_flag && (m - m2) < TAU) {
        int p = atomicAdd(&g_fixB_cnt[opt], 1);
        if (p < FIXB_CAP) g_fixB_list[opt*FIXB_CAP + p] = g;
    }
}

// ---------------------------------------------------------------------------
// Phase B fast (1-pass) and fix (3-pass) via a shared body.
// ---------------------------------------------------------------------------
template <bool EXACT>
__device__ __forceinline__ void phaseB_body(
    const int* list, int listStride, int cnt,
    const float* b1, const float* Wpi, const float* Wv, float* out)
{
    const int opt   = blockIdx.y;
    const int start = blockIdx.x * MT;
    const int myCnt = min(cnt, EXACT ? FIXB_CAP : B_AG);
    if (start >= myCnt) return;
    const int nvalid = min(MT, myCnt - start);

    extern __shared__ float smf[];
    const uint32_t su = (uint32_t)__cvta_generic_to_shared(smf);
    const int t = threadIdx.x;
    float* fin = smf + FIN_OFFB/4;
    int* idx_s = (int*)(smf + MISC_OFFB/4);

    if (t < MT)
        idx_s[t] = list[opt*listStride + start + ((t < nvalid) ? t : 0)];
    __syncthreads();

    const size_t arow0 = (size_t)idx_s[t >> 2]*DID + (t & 3)*8;
    const size_t arow1 = (size_t)idx_s[(t >> 2) + 32]*DID + (t & 3)*8;
    const __half* aHi0 = g_obsHi + arow0;
    const __half* aHi1 = g_obsHi + arow1;
    const __half* aLo0 = g_obsLo + arow0;
    const __half* aLo1 = g_obsLo + arow1;

    const float* bg   = b1  + (size_t)opt*HID;
    const float* wpig = Wpi + (size_t)opt*HID*NACT;
    const float* wvg  = Wv  + (size_t)opt*HID;

    float accB[17];
    #pragma unroll
    for (int k = 0; k < 17; ++k) accB[k] = 0.f;
    const int r = t & 63;

    #pragma unroll 1
    for (int ht = 0; ht < HID/NTILE; ++ht) {
        const int hbase = ht * NTILE;
        loadB_heads(smf, t, hbase, bg, wpig, wvg);
        const size_t brow = ((size_t)(2 + opt)*HID + hbase + (t >> 2))*DID + (t & 3)*8;
        float acc[2][8][4];
        ZERO_ACC8(acc);
        if (EXACT)
            gemm3(su, t, aHi0, aHi1, aLo0, aLo1,
                  g_wHiT + brow, g_wLoT + brow, acc);
        else
            gemm1(su, t, aHi0, aHi1, g_wHiT + brow, acc);
        stage_h(smf, acc, t);
        __syncthreads();
        headB_accum(smf, t, accB);
        __syncthreads();
    }

    if (t >= 64) {
        #pragma unroll
        for (int k = 0; k < 17; ++k) fin[r*FINS + k] = accB[k];
    }
    __syncthreads();

    if (t < nvalid) {
        float lg17[17];
        #pragma unroll
        for (int k = 0; k < 17; ++k) lg17[k] = accB[k] + fin[t*FINS + k];
        finishB(idx_s[t], opt, lg17, out, !EXACT);
    }
}

__global__ void __launch_bounds__(NT, 2)
phaseB_fast(const float* __restrict__ b1, const float* __restrict__ Wpi,
            const float* __restrict__ Wv, float* __restrict__ out) {
    phaseB_body<false>(g_opt_list, B_AG, g_opt_cnt[blockIdx.y], b1, Wpi, Wv, out);
}
__global__ void __launch_bounds__(NT, 2)
phaseB_fix(const float* __restrict__ b1, const float* __restrict__ Wpi,
           const float* __restrict__ Wv, float* __restrict__ out) {
    phaseB_body<true>(g_fixB_list, FIXB_CAP, g_fixB_cnt[blockIdx.y], b1, Wpi, Wv, out);
}

extern "C" void kernel_launch(void* const* d_in, const int* in_sizes, int n_in,
                              void* d_out, int out_size) {
    const float* obs      = (const float*)d_in[0];
    const int*   dones    = (const int*)  d_in[1];
    const int*   exec_opt = (const int*)  d_in[2];
    const float* Wm1      = (const float*)d_in[3];
    const float* bm1      = (const float*)d_in[4];
    const float* Wm_pi    = (const float*)d_in[5];
    const float* Wm_v     = (const float*)d_in[6];
    const float* Wt1      = (const float*)d_in[7];
    const float* Wt2      = (const float*)d_in[8];
    const float* W1       = (const float*)d_in[9];
    const float* b1       = (const float*)d_in[10];
    const float* Wpi      = (const float*)d_in[11];
    const float* Wv       = (const float*)d_in[12];
    float* out = (float*)d_out;

    cudaFuncSetAttribute(phaseA_fast, cudaFuncAttributeMaxDynamicSharedMemorySize, SMEM_BYTES);
    cudaFuncSetAttribute(phaseA_fix,  cudaFuncAttributeMaxDynamicSharedMemorySize, SMEM_BYTES);
    cudaFuncSetAttribute(phaseB_fast, cudaFuncAttributeMaxDynamicSharedMemorySize, SMEM_BYTES);
    cudaFuncSetAttribute(phaseB_fix,  cudaFuncAttributeMaxDynamicSharedMemorySize, SMEM_BYTES);

    convert_obs_kernel<<<(B_AG*DID)/(256*8), 256>>>(obs);
    dim3 gW(HID/32, DID/32, 10);
    convert_w_kernel<<<gW, dim3(32, 8)>>>(Wm1, Wt1, W1);
    phaseA_fast<<<B_AG/MT, NT, SMEM_BYTES>>>(
        dones, exec_opt, bm1, Wm_pi, Wm_v, Wt2, out);
    phaseA_fix<<<FIXA_CAP/MT, NT, SMEM_BYTES>>>(
        dones, exec_opt, bm1, Wm_pi, Wm_v, Wt2, out);
    compact_kernel<<<B_AG/128, 128>>>(exec_opt);
    dim3 gB(B_AG/MT, NOPT);
    phaseB_fast<<<gB, NT, SMEM_BYTES>>>(b1, Wpi, Wv, out);
    dim3 gF(FIXB_CAP/MT, NOPT);
    phaseB_fix<<<gF, NT, SMEM_BYTES>>>(b1, Wpi, Wv, out);
}

// round 15
// speedup vs baseline: 2.2106x; 2.2106x over previous
#include <cuda_runtime.h>
#include <cuda_fp16.h>
#include <math.h>
#include <stdint.h>

#define B_AG 32768
#define DID  512
#define HID  1024
#define NOPT 8
#define NACT 16

#define MT    64
#define NTILE 128
#define KCH   32
#define NCH   (DID/KCH)
#define NT    128

#define TAU 4e-3f
#define FIXA_CAP 4096
#define FIXB_CAP 512

// ---- smem byte layout (R7) ----
#define A_HI 0
#define A_LO 5120
#define B_HI 10240
#define B_LO 20480
#define STAGE_BYTES 30720
#define ST_OFF(s)  (1024 + (s)*STAGE_BYTES)
#define HST_OFFB 1024
#define HSTS 133
#define FIN_OFFB 35072
#define FINS 20
#define HWS  20
#define HW_OFFB   62464
#define BIAS_OFFB 72704
#define MISC_OFFB 73216
#define SMEM_BYTES 73984

__device__ int    g_opt_cnt[NOPT];
__device__ int    g_opt_list[NOPT*B_AG];
__device__ int    g_meta_act[B_AG];
__device__ int    g_term_dec[B_AG];
__device__ int    g_fixA_cnt;
__device__ int    g_fixA_list[FIXA_CAP];
__device__ int    g_fixB_cnt[NOPT];
__device__ int    g_fixB_list[NOPT*FIXB_CAP];
__device__ float  g_fixA_part[16][FIXA_CAP][17];        // [net*8+ht][slot][k]
__device__ float  g_fixB_part[8][NOPT][FIXB_CAP][17];   // [ht][opt][slot][k]
__device__ __half g_obsHi[(size_t)B_AG*DID];
__device__ __half g_obsLo[(size_t)B_AG*DID];
__device__ __half g_wHiT[(size_t)10*HID*DID];   // K-major: [mat][h][k]
__device__ __half g_wLoT[(size_t)10*HID*DID];

// ---------------------------------------------------------------------------
__device__ __forceinline__ void cp16(uint32_t dst, const void* src) {
    asm volatile("cp.async.cg.shared.global [%0], [%1], 16;" :: "r"(dst), "l"(src));
}
#define CP_COMMIT() asm volatile("cp.async.commit_group;")

__device__ __forceinline__ void ldm4(uint32_t a, uint32_t r[4]) {
    asm volatile("ldmatrix.sync.aligned.m8n8.x4.shared.b16 {%0,%1,%2,%3}, [%4];"
        : "=r"(r[0]), "=r"(r[1]), "=r"(r[2]), "=r"(r[3]) : "r"(a));
}
__device__ __forceinline__ void mma16816(float d[4], const uint32_t a[4],
                                         uint32_t b0, uint32_t b1) {
    asm volatile("mma.sync.aligned.m16n8k16.row.col.f32.f16.f16.f32 "
        "{%0,%1,%2,%3}, {%4,%5,%6,%7}, {%8,%9}, {%0,%1,%2,%3};"
        : "+f"(d[0]), "+f"(d[1]), "+f"(d[2]), "+f"(d[3])
        : "r"(a[0]), "r"(a[1]), "r"(a[2]), "r"(a[3]), "r"(b0), "r"(b1));
}

// ---------------------------------------------------------------------------
__global__ void __launch_bounds__(256)
convert_obs_kernel(const float* __restrict__ obs) {
    size_t i = ((size_t)blockIdx.x*256 + threadIdx.x)*8;
    float v[8]; __half hi[8], lo[8];
    #pragma unroll
    for (int k = 0; k < 8; ++k) v[k] = obs[i + k];
    #pragma unroll
    for (int k = 0; k < 8; ++k) {
        hi[k] = __float2half_rn(v[k]);
        lo[k] = __float2half_rn(v[k] - __half2float(hi[k]));
    }
    *(uint4*)&g_obsHi[i] = *(uint4*)hi;
    *(uint4*)&g_obsLo[i] = *(uint4*)lo;
    if (blockIdx.x == 0 && threadIdx.x < NOPT) {
        g_opt_cnt[threadIdx.x] = 0;
        g_fixB_cnt[threadIdx.x] = 0;
        if (threadIdx.x == 0) g_fixA_cnt = 0;
    }
}

__global__ void __launch_bounds__(256)
convert_w_kernel(const float* __restrict__ Wm1,
                 const float* __restrict__ Wt1,
                 const float* __restrict__ W1) {
    __shared__ float tile[32][33];
    const int m = blockIdx.z;
    const float* src = (m == 0) ? Wm1 : (m == 1) ? Wt1 : W1 + (size_t)(m-2)*DID*HID;
    const int h0 = blockIdx.x * 32;
    const int k0 = blockIdx.y * 32;
    const int tx = threadIdx.x, ty0 = threadIdx.y;
    #pragma unroll
    for (int r = 0; r < 32; r += 8)
        tile[r + ty0][tx] = src[(size_t)(k0 + r + ty0)*HID + h0 + tx];
    __syncthreads();
    __half* dHi = g_wHiT + (size_t)m*HID*DID;
    __half* dLo = g_wLoT + (size_t)m*HID*DID;
    #pragma unroll
    for (int r = 0; r < 32; r += 8) {
        float x = tile[tx][r + ty0];
        __half hi = __float2half_rn(x);
        __half lo = __float2half_rn(x - __half2float(hi));
        size_t o = (size_t)(h0 + r + ty0)*DID + k0 + tx;
        dHi[o] = hi; dLo[o] = lo;
    }
}

// ---------------------------------------------------------------------------
// 3-pass GEMM tile (exact)
// ---------------------------------------------------------------------------
__device__ __forceinline__ void gemm3(uint32_t su, int t,
    const __half* aHi0, const __half* aHi1,
    const __half* aLo0, const __half* aLo1,
    const __half* bHi,  const __half* bLo,
    float acc[2][8][4])
{
    const int lane = t & 31, w = t >> 5;
    const int wm = (w & 1) * 32, wn = (w >> 1) * 64;
    const uint32_t drow = (uint32_t)((t >> 2)*80 + (t & 3)*16);

    #define FILL3(s, kc) do {                                   \
        uint32_t _b = su + ST_OFF(s) + drow;                    \
        const int _ko = (kc)*KCH;                               \
        cp16(_b + A_HI,        aHi0 + _ko);                     \
        cp16(_b + A_HI + 2560, aHi1 + _ko);                     \
        cp16(_b + A_LO,        aLo0 + _ko);                     \
        cp16(_b + A_LO + 2560, aLo1 + _ko);                     \
        _Pragma("unroll")                                       \
        for (int _i = 0; _i < 4; ++_i) {                        \
            cp16(_b + B_HI + _i*2560, bHi + _i*32*DID + _ko);   \
            cp16(_b + B_LO + _i*2560, bLo + _i*32*DID + _ko);   \
        }                                                       \
        CP_COMMIT();                                            \
    } while (0)

    FILL3(0, 0);

    #pragma unroll 1
    for (int kc = 0; kc < NCH; ++kc) {
        const int cur = kc & 1;
        if (kc + 1 < NCH) {
            FILL3(cur ^ 1, kc + 1);
            asm volatile("cp.async.wait_group 1;");
        } else {
            asm volatile("cp.async.wait_group 0;");
        }
        __syncthreads();

        const uint32_t sb = su + ST_OFF(cur);
        #pragma unroll
        for (int ks = 0; ks < 2; ++ks) {
            const uint32_t ko = ks*32 + (lane >> 4)*16;
            const uint32_t aadr = sb + A_HI + (uint32_t)((wm + (lane & 15))*80) + ko;
            uint32_t ah0[4], ah1[4], al0[4], al1[4];
            ldm4(aadr,          ah0);
            ldm4(aadr + 16*80,  ah1);
            ldm4(aadr + 5120,         al0);
            ldm4(aadr + 5120 + 16*80, al1);
            uint32_t bh[4][4], bl[4][4];
            #pragma unroll
            for (int j = 0; j < 4; ++j) {
                const uint32_t badr = sb + B_HI
                    + (uint32_t)((wn + j*16 + (lane & 15))*80) + ko;
                ldm4(badr,         bh[j]);
                ldm4(badr + 10240, bl[j]);
            }
            #pragma unroll
            for (int j = 0; j < 4; ++j) {
                mma16816(acc[0][2*j  ], ah0, bh[j][0], bh[j][2]);
                mma16816(acc[0][2*j+1], ah0, bh[j][1], bh[j][3]);
                mma16816(acc[1][2*j  ], ah1, bh[j][0], bh[j][2]);
                mma16816(acc[1][2*j+1], ah1, bh[j][1], bh[j][3]);
            }
            #pragma unroll
            for (int j = 0; j < 4; ++j) {
                mma16816(acc[0][2*j  ], ah0, bl[j][0], bl[j][2]);
                mma16816(acc[0][2*j+1], ah0, bl[j][1], bl[j][3]);
                mma16816(acc[1][2*j  ], ah1, bl[j][0], bl[j][2]);
                mma16816(acc[1][2*j+1], ah1, bl[j][1], bl[j][3]);
            }
            #pragma unroll
            for (int j = 0; j < 4; ++j) {
                mma16816(acc[0][2*j  ], al0, bh[j][0], bh[j][2]);
                mma16816(acc[0][2*j+1], al0, bh[j][1], bh[j][3]);
                mma16816(acc[1][2*j  ], al1, bh[j][0], bh[j][2]);
                mma16816(acc[1][2*j+1], al1, bh[j][1], bh[j][3]);
            }
        }
        __syncthreads();
    }
    #undef FILL3
}

// ---------------------------------------------------------------------------
// 1-pass GEMM tile (hi*hi only)
// ---------------------------------------------------------------------------
__device__ __forceinline__ void gemm1(uint32_t su, int t,
    const __half* aHi0, const __half* aHi1,
    const __half* bHi,
    float acc[2][8][4])
{
    const int lane = t & 31, w = t >> 5;
    const int wm = (w & 1) * 32, wn = (w >> 1) * 64;
    const uint32_t drow = (uint32_t)((t >> 2)*80 + (t & 3)*16);

    #define FILL1(s, kc) do {                                   \
        uint32_t _b = su + ST_OFF(s) + drow;                    \
        const int _ko = (kc)*KCH;                               \
        cp16(_b + A_HI,        aHi0 + _ko);                     \
        cp16(_b + A_HI + 2560, aHi1 + _ko);                     \
        _Pragma("unroll")                                       \
        for (int _i = 0; _i < 4; ++_i)                          \
            cp16(_b + B_HI + _i*2560, bHi + _i*32*DID + _ko);   \
        CP_COMMIT();                                            \
    } while (0)

    FILL1(0, 0);

    #pragma unroll 1
    for (int kc = 0; kc < NCH; ++kc) {
        const int cur = kc & 1;
        if (kc + 1 < NCH) {
            FILL1(cur ^ 1, kc + 1);
            asm volatile("cp.async.wait_group 1;");
        } else {
            asm volatile("cp.async.wait_group 0;");
        }
        __syncthreads();

        const uint32_t sb = su + ST_OFF(cur);
        #pragma unroll
        for (int ks = 0; ks < 2; ++ks) {
            const uint32_t ko = ks*32 + (lane >> 4)*16;
            const uint32_t aadr = sb + A_HI + (uint32_t)((wm + (lane & 15))*80) + ko;
            uint32_t ah0[4], ah1[4];
            ldm4(aadr,          ah0);
            ldm4(aadr + 16*80,  ah1);
            uint32_t bh[4][4];
            #pragma unroll
            for (int j = 0; j < 4; ++j) {
                const uint32_t badr = sb + B_HI
                    + (uint32_t)((wn + j*16 + (lane & 15))*80) + ko;
                ldm4(badr, bh[j]);
            }
            #pragma unroll
            for (int j = 0; j < 4; ++j) {
                mma16816(acc[0][2*j  ], ah0, bh[j][0], bh[j][2]);
                mma16816(acc[0][2*j+1], ah0, bh[j][1], bh[j][3]);
                mma16816(acc[1][2*j  ], ah1, bh[j][0], bh[j][2]);
                mma16816(acc[1][2*j+1], ah1, bh[j][1], bh[j][3]);
            }
        }
        __syncthreads();
    }
    #undef FILL1
}

__device__ __forceinline__ void stage_h(float* smf, const float acc[2][8][4],
                                        int t) {
    const int lane = t & 31, w = t >> 5;
    const int wm = (w & 1) * 32, wn = (w >> 1) * 64;
    float* hst = smf + HST_OFFB/4;
    const float* bias_s = smf + BIAS_OFFB/4;
    #pragma unroll
    for (int im = 0; im < 2; ++im) {
        #pragma unroll
        for (int j = 0; j < 8; ++j) {
            #pragma unroll
            for (int e = 0; e < 4; ++e) {
                int row = wm + im*16 + (lane >> 2) + (e >> 1)*8;
                int col = wn + j*8 + 2*(lane & 3) + (e & 1);
                float h = acc[im][j][e] + bias_s[col];
                hst[row*HSTS + col] = fmaxf(h, 0.f);
            }
        }
    }
}

#define ZERO_ACC8(acc) do {                                \
    _Pragma("unroll") for (int _i = 0; _i < 2; ++_i)       \
    _Pragma("unroll") for (int _j = 0; _j < 8; ++_j)       \
    _Pragma("unroll") for (int _e = 0; _e < 4; ++_e)       \
        (acc)[_i][_j][_e] = 0.f;                           \
} while (0)

__device__ __forceinline__ void loadA_heads(float* smf, int t, int net, int hbase,
    const float* bm1, const float* Wm_pi, const float* Wm_v, const float* Wt2)
{
    float* hw     = smf + HW_OFFB/4;
    float* bias_s = smf + BIAS_OFFB/4;
    if (net == 0) {
        const float* wp = Wm_pi + (size_t)(hbase + t)*NOPT;
        #pragma unroll
        for (int o = 0; o < NOPT; ++o) hw[t*HWS + o] = wp[o];
        hw[t*HWS + 8] = Wm_v[hbase + t];
        bias_s[t] = bm1[hbase + t];
    } else {
        const float* wp = Wt2 + (size_t)(hbase + t)*NOPT;
        #pragma unroll
        for (int o = 0; o < NOPT; ++o) hw[t*HWS + o] = wp[o];
        bias_s[t] = 0.f;
    }
}

__device__ __forceinline__ void headA_accum(const float* smf, int t, int net,
                                            float accM[9], float accT[8]) {
    const float* hst = smf + HST_OFFB/4;
    const float* hw  = smf + HW_OFFB/4;
    const int r = t & 63, cbase = (t >> 6)*64;
    if (net == 0) {
        #pragma unroll 4
        for (int c = 0; c < 64; ++c) {
            float h = hst[r*HSTS + cbase + c];
            const float* hwc = hw + (cbase + c)*HWS;
            float4 w0 = *(const float4*)(hwc);
            float4 w1 = *(const float4*)(hwc + 4);
            accM[0] += h*w0.x; accM[1] += h*w0.y;
            accM[2] += h*w0.z; accM[3] += h*w0.w;
            accM[4] += h*w1.x; accM[5] += h*w1.y;
            accM[6] += h*w1.z; accM[7] += h*w1.w;
            accM[8] += h*hwc[8];
        }
    } else {
        #pragma unroll 4
        for (int c = 0; c < 64; ++c) {
            float h = hst[r*HSTS + cbase + c];
            const float* hwc = hw + (cbase + c)*HWS;
            float4 w0 = *(const float4*)(hwc);
            float4 w1 = *(const float4*)(hwc + 4);
            accT[0] += h*w0.x; accT[1] += h*w0.y;
            accT[2] += h*w0.z; accT[3] += h*w0.w;
            accT[4] += h*w1.x; accT[5] += h*w1.y;
            accT[6] += h*w1.z; accT[7] += h*w1.w;
        }
    }
}

__device__ __forceinline__ void finishA(int g, const float tot[17],
    const int* dones, const int* exec_opt, float* out, bool allow_flag)
{
    float m = tot[0], m2 = -1e30f; int am = 0;
    #pragma unroll
    for (int o = 1; o < 8; ++o) {
        if (tot[o] > m) { m2 = m; m = tot[o]; am = o; }
        else if (tot[o] > m2) m2 = tot[o];
    }
    float s = 0.f;
    #pragma unroll
    for (int o = 0; o < 8; ++o) s += expf(tot[o] - m);
    float lp = -logf(s);
    int eo = exec_opt[g];
    float tl = tot[9 + eo];
    float tp = 1.0f/(1.0f + expf(-tl));
    bool dn = (dones[g] != 0);
    bool term = dn || (tp > 0.5f);
    out[3*B_AG + g] = (float)am;
    out[4*B_AG + g] = tot[8];
    out[5*B_AG + g] = lp;
    out[6*B_AG + g] = tp;
    g_meta_act[g] = am;
    g_term_dec[g] = term ? 1 : 0;
    if (allow_flag) {
        bool f = ((m - m2) < TAU) || (!dn && (fabsf(tl) < TAU));
        if (f) {
            int p = atomicAdd(&g_fixA_cnt, 1);
            if (p < FIXA_CAP) g_fixA_list[p] = g;
        }
    }
}

// ---------------------------------------------------------------------------
// Phase A fast: 1-pass, full chain.
// ---------------------------------------------------------------------------
__global__ void __launch_bounds__(NT, 2)
phaseA_fast(const int*   __restrict__ dones,
            const int*   __restrict__ exec_opt,
            const float* __restrict__ bm1,
            const float* __restrict__ Wm_pi,
            const float* __restrict__ Wm_v,
            const float* __restrict__ Wt2,
            float* __restrict__ out)
{
    extern __shared__ float smf[];
    const uint32_t su = (uint32_t)__cvta_generic_to_shared(smf);
    const int t = threadIdx.x;
    const int g0 = blockIdx.x * MT;
    float* fin = smf + FIN_OFFB/4;

    const size_t arow = (size_t)(g0 + (t >> 2))*DID + (t & 3)*8;
    const __half* aHi0 = g_obsHi + arow;
    const __half* aHi1 = aHi0 + (size_t)32*DID;

    float accM[9], accT[8];
    #pragma unroll
    for (int k = 0; k < 9; ++k) accM[k] = 0.f;
    #pragma unroll
    for (int k = 0; k < 8; ++k) accT[k] = 0.f;
    const int r = t & 63;

    #pragma unroll 1
    for (int net = 0; net < 2; ++net) {
        #pragma unroll 1
        for (int ht = 0; ht < HID/NTILE; ++ht) {
            const int hbase = ht * NTILE;
            loadA_heads(smf, t, net, hbase, bm1, Wm_pi, Wm_v, Wt2);
            const size_t brow = ((size_t)net*HID + hbase + (t >> 2))*DID + (t & 3)*8;
            float acc[2][8][4];
            ZERO_ACC8(acc);
            gemm1(su, t, aHi0, aHi1, g_wHiT + brow, acc);
            stage_h(smf, acc, t);
            __syncthreads();
            headA_accum(smf, t, net, accM, accT);
            __syncthreads();
        }
    }

    if (t >= 64) {
        #pragma unroll
        for (int k = 0; k < 9; ++k) fin[r*FINS + k] = accM[k];
        #pragma unroll
        for (int k = 0; k < 8; ++k) fin[r*FINS + 9 + k] = accT[k];
    }
    __syncthreads();

    if (t < MT) {
        float tot[17];
        #pragma unroll
        for (int k = 0; k < 9; ++k) tot[k] = accM[k] + fin[t*FINS + k];
        #pragma unroll
        for (int k = 0; k < 8; ++k) tot[9 + k] = accT[k] + fin[t*FINS + 9 + k];
        finishA(g0 + t, tot, dones, exec_opt, out, true);
    }
}

// ---------------------------------------------------------------------------
// Phase A fix, tile-parallel: grid (FIXA_CAP/MT, 16). blockIdx.y = net*8+ht.
// Writes per-tile partial head sums; finalized by phaseA_fix_final.
// ---------------------------------------------------------------------------
__global__ void __launch_bounds__(NT, 2)
phaseA_fix_part(const float* __restrict__ bm1,
                const float* __restrict__ Wm_pi,
                const float* __restrict__ Wm_v,
                const float* __restrict__ Wt2)
{
    const int cnt = min(g_fixA_cnt, FIXA_CAP);
    const int start = blockIdx.x * MT;
    if (start >= cnt) return;
    const int nvalid = min(MT, cnt - start);
    const int tt = blockIdx.y;
    const int net = tt >> 3, hbase = (tt & 7)*NTILE;

    extern __shared__ float smf[];
    const uint32_t su = (uint32_t)__cvta_generic_to_shared(smf);
    const int t = threadIdx.x;
    float* fin = smf + FIN_OFFB/4;
    int* idx_s = (int*)(smf + MISC_OFFB/4);

    if (t < MT) idx_s[t] = g_fixA_list[start + ((t < nvalid) ? t : 0)];
    __syncthreads();

    const size_t arow0 = (size_t)idx_s[t >> 2]*DID + (t & 3)*8;
    const size_t arow1 = (size_t)idx_s[(t >> 2) + 32]*DID + (t & 3)*8;

    loadA_heads(smf, t, net, hbase, bm1, Wm_pi, Wm_v, Wt2);
    const size_t brow = ((size_t)net*HID + hbase + (t >> 2))*DID + (t & 3)*8;

    float acc[2][8][4];
    ZERO_ACC8(acc);
    gemm3(su, t, g_obsHi + arow0, g_obsHi + arow1,
          g_obsLo + arow0, g_obsLo + arow1,
          g_wHiT + brow, g_wLoT + brow, acc);
    stage_h(smf, acc, t);
    __syncthreads();

    float accM[9], accT[8];
    #pragma unroll
    for (int k = 0; k < 9; ++k) accM[k] = 0.f;
    #pragma unroll
    for (int k = 0; k < 8; ++k) accT[k] = 0.f;
    headA_accum(smf, t, net, accM, accT);
    __syncthreads();

    const int r = t & 63;
    if (t >= 64) {
        #pragma unroll
        for (int k = 0; k < 9; ++k) fin[r*FINS + k] = accM[k];
        #pragma unroll
        for (int k = 0; k < 8; ++k) fin[r*FINS + 9 + k] = accT[k];
    }
    __syncthreads();

    if (t < nvalid) {
        float* dst = g_fixA_part[tt][start + t];
        if (net == 0) {
            #pragma unroll
            for (int k = 0; k < 9; ++k) dst[k] = accM[k] + fin[t*FINS + k];
        } else {
            #pragma unroll
            for (int k = 0; k < 8; ++k) dst[9 + k] = accT[k] + fin[t*FINS + 9 + k];
        }
    }
}

__global__ void __launch_bounds__(128)
phaseA_fix_final(const int* __restrict__ dones,
                 const int* __restrict__ exec_opt,
                 float* __restrict__ out)
{
    const int cnt = min(g_fixA_cnt, FIXA_CAP);
    const int s = blockIdx.x*128 + threadIdx.x;
    if (s >= cnt) return;
    float tot[17];
    #pragma unroll
    for (int k = 0; k < 17; ++k) tot[k] = 0.f;
    #pragma unroll
    for (int tile = 0; tile < 8; ++tile) {
        const float* p = g_fixA_part[tile][s];
        #pragma unroll
        for (int k = 0; k < 9; ++k) tot[k] += p[k];
    }
    #pragma unroll
    for (int tile = 8; tile < 16; ++tile) {
        const float* p = g_fixA_part[tile][s];
        #pragma unroll
        for (int k = 0; k < 8; ++k) tot[9 + k] += p[9 + k];
    }
    finishA(g_fixA_list[s], tot, dones, exec_opt, out, false);
}

// ---------------------------------------------------------------------------
__global__ void __launch_bounds__(128)
compact_kernel(const int* __restrict__ exec_opt) {
    __shared__ int s_cnt[NOPT], s_base[NOPT];
    const int t = threadIdx.x;
    const int g = blockIdx.x*128 + t;
    if (t < NOPT) s_cnt[t] = 0;
    __syncthreads();
    const int myno = g_term_dec[g] ? g_meta_act[g] : exec_opt[g];
    const int pos = atomicAdd(&s_cnt[myno], 1);
    __syncthreads();
    if (t < NOPT) s_base[t] = atomicAdd(&g_opt_cnt[t], s_cnt[t]);
    __syncthreads();
    g_opt_list[myno*B_AG + s_base[myno] + pos] = g;
}

// ---------------------------------------------------------------------------
// Phase B pieces
// ---------------------------------------------------------------------------
__device__ __forceinline__ void loadB_heads(float* smf, int t, int hbase,
    const float* bg, const float* wpig, const float* wvg)
{
    float* hw     = smf + HW_OFFB/4;
    float* bias_s = smf + BIAS_OFFB/4;
    const float* wp = wpig + (size_t)(hbase + t)*NACT;
    #pragma unroll
    for (int a = 0; a < NACT; ++a) hw[t*HWS + a] = wp[a];
    hw[t*HWS + 16] = wvg[hbase + t];
    bias_s[t] = bg[hbase + t];
}

__device__ __forceinline__ void headB_accum(const float* smf, int t,
                                            float accB[17]) {
    const float* hst = smf + HST_OFFB/4;
    const float* hw  = smf + HW_OFFB/4;
    const int r = t & 63, cbase = (t >> 6)*64;
    #pragma unroll 2
    for (int c = 0; c < 64; ++c) {
        float h = hst[r*HSTS + cbase + c];
        const float* hwc = hw + (cbase + c)*HWS;
        float4 w0 = *(const float4*)(hwc);
        float4 w1 = *(const float4*)(hwc + 4);
        float4 w2 = *(const float4*)(hwc + 8);
        float4 w3 = *(const float4*)(hwc + 12);
        accB[0]  += h*w0.x; accB[1]  += h*w0.y;
        accB[2]  += h*w0.z; accB[3]  += h*w0.w;
        accB[4]  += h*w1.x; accB[5]  += h*w1.y;
        accB[6]  += h*w1.z; accB[7]  += h*w1.w;
        accB[8]  += h*w2.x; accB[9]  += h*w2.y;
        accB[10] += h*w2.z; accB[11] += h*w2.w;
        accB[12] += h*w3.x; accB[13] += h*w3.y;
        accB[14] += h*w3.z; accB[15] += h*w3.w;
        accB[16] += h*hwc[16];
    }
}

__device__ __forceinline__ void finishB(int g, int opt, const float lg17[17],
                                        float* out, bool allow_flag) {
    float m = lg17[0], m2 = -1e30f; int am = 0;
    #pragma unroll
    for (int a = 1; a < NACT; ++a) {
        if (lg17[a] > m) { m2 = m; m = lg17[a]; am = a; }
        else if (lg17[a] > m2) m2 = lg17[a];
    }
    float s = 0.f;
    #pragma unroll
    for (int a = 0; a < NACT; ++a) s += expf(lg17[a] - m);
    float lp = -logf(s);
    out[          g] = (float)am;
    out[  B_AG +  g] = lg17[16];
    out[2*B_AG +  g] = lp;
    if (allow_flag && (m - m2) < TAU) {
        int p = atomicAdd(&g_fixB_cnt[opt], 1);
        if (p < FIXB_CAP) g_fixB_list[opt*FIXB_CAP + p] = g;
    }
}

// ---------------------------------------------------------------------------
// Phase B fast: 1-pass, full 8-tile chain.
// ---------------------------------------------------------------------------
__global__ void __launch_bounds__(NT, 2)
phaseB_fast(const float* __restrict__ b1, const float* __restrict__ Wpi,
            const float* __restrict__ Wv, float* __restrict__ out)
{
    const int opt   = blockIdx.y;
    const int start = blockIdx.x * MT;
    const int cnt   = g_opt_cnt[opt];
    if (start >= cnt) return;
    const int nvalid = min(MT, cnt - start);

    extern __shared__ float smf[];
    const uint32_t su = (uint32_t)__cvta_generic_to_shared(smf);
    const int t = threadIdx.x;
    float* fin = smf + FIN_OFFB/4;
    int* idx_s = (int*)(smf + MISC_OFFB/4);

    if (t < MT)
        idx_s[t] = g_opt_list[opt*B_AG + start + ((t < nvalid) ? t : 0)];
    __syncthreads();

    const size_t arow0 = (size_t)idx_s[t >> 2]*DID + (t & 3)*8;
    const size_t arow1 = (size_t)idx_s[(t >> 2) + 32]*DID + (t & 3)*8;
    const __half* aHi0 = g_obsHi + arow0;
    const __half* aHi1 = g_obsHi + arow1;

    const float* bg   = b1  + (size_t)opt*HID;
    const float* wpig = Wpi + (size_t)opt*HID*NACT;
    const float* wvg  = Wv  + (size_t)opt*HID;

    float accB[17];
    #pragma unroll
    for (int k = 0; k < 17; ++k) accB[k] = 0.f;
    const int r = t & 63;

    #pragma unroll 1
    for (int ht = 0; ht < HID/NTILE; ++ht) {
        const int hbase = ht * NTILE;
        loadB_heads(smf, t, hbase, bg, wpig, wvg);
        const size_t brow = ((size_t)(2 + opt)*HID + hbase + (t >> 2))*DID + (t & 3)*8;
        float acc[2][8][4];
        ZERO_ACC8(acc);
        gemm1(su, t, aHi0, aHi1, g_wHiT + brow, acc);
        stage_h(smf, acc, t);
        __syncthreads();
        headB_accum(smf, t, accB);
        __syncthreads();
    }

    if (t >= 64) {
        #pragma unroll
        for (int k = 0; k < 17; ++k) fin[r*FINS + k] = accB[k];
    }
    __syncthreads();

    if (t < nvalid) {
        float lg17[17];
        #pragma unroll
        for (int k = 0; k < 17; ++k) lg17[k] = accB[k] + fin[t*FINS + k];
        finishB(idx_s[t], opt, lg17, out, true);
    }
}

// ---------------------------------------------------------------------------
// Phase B fix, tile-parallel: grid (FIXB_CAP/MT, 8 htiles, NOPT).
// ---------------------------------------------------------------------------
__global__ void __launch_bounds__(NT, 2)
phaseB_fix_part(const float* __restrict__ b1, const float* __restrict__ Wpi,
                const float* __restrict__ Wv)
{
    const int opt = blockIdx.z;
    const int cnt = min(g_fixB_cnt[opt], FIXB_CAP);
    const int start = blockIdx.x * MT;
    if (start >= cnt) return;
    const int nvalid = min(MT, cnt - start);
    const int ht = blockIdx.y, hbase = ht*NTILE;

    extern __shared__ float smf[];
    const uint32_t su = (uint32_t)__cvta_generic_to_shared(smf);
    const int t = threadIdx.x;
    float* fin = smf + FIN_OFFB/4;
    int* idx_s = (int*)(smf + MISC_OFFB/4);

    if (t < MT)
        idx_s[t] = g_fixB_list[opt*FIXB_CAP + start + ((t < nvalid) ? t : 0)];
    __syncthreads();

    const size_t arow0 = (size_t)idx_s[t >> 2]*DID + (t & 3)*8;
    const size_t arow1 = (size_t)idx_s[(t >> 2) + 32]*DID + (t & 3)*8;

    const float* bg   = b1  + (size_t)opt*HID;
    const float* wpig = Wpi + (size_t)opt*HID*NACT;
    const float* wvg  = Wv  + (size_t)opt*HID;

    loadB_heads(smf, t, hbase, bg, wpig, wvg);
    const size_t brow = ((size_t)(2 + opt)*HID + hbase + (t >> 2))*DID + (t & 3)*8;

    float acc[2][8][4];
    ZERO_ACC8(acc);
    gemm3(su, t, g_obsHi + arow0, g_obsHi + arow1,
          g_obsLo + arow0, g_obsLo + arow1,
          g_wHiT + brow, g_wLoT + brow, acc);
    stage_h(smf, acc, t);
    __syncthreads();

    float accB[17];
    #pragma unroll
    for (int k = 0; k < 17; ++k) accB[k] = 0.f;
    headB_accum(smf, t, accB);
    __syncthreads();

    const int r = t & 63;
    if (t >= 64) {
        #pragma unroll
        for (int k = 0; k < 17; ++k) fin[r*FINS + k] = accB[k];
    }
    __syncthreads();

    if (t < nvalid) {
        float* dst = g_fixB_part[ht][opt][start + t];
        #pragma unroll
        for (int k = 0; k < 17; ++k) dst[k] = accB[k] + fin[t*FINS + k];
    }
}

__global__ void __launch_bounds__(128)
phaseB_fix_final(float* __restrict__ out)
{
    const int opt = blockIdx.y;
    const int cnt = min(g_fixB_cnt[opt], FIXB_CAP);
    const int s = blockIdx.x*128 + threadIdx.x;
    if (s >= cnt) return;
    float lg17[17];
    #pragma unroll
    for (int k = 0; k < 17; ++k) lg17[k] = 0.f;
    #pragma unroll
    for (int tile = 0; tile < 8; ++tile) {
        const float* p = g_fixB_part[tile][opt][s];
        #pragma unroll
        for (int k = 0; k < 17; ++k) lg17[k] += p[k];
    }
    finishB(g_fixB_list[opt*FIXB_CAP + s], opt, lg17, out, false);
}

extern "C" void kernel_launch(void* const* d_in, const int* in_sizes, int n_in,
                              void* d_out, int out_size) {
    const float* obs      = (const float*)d_in[0];
    const int*   dones    = (const int*)  d_in[1];
    const int*   exec_opt = (const int*)  d_in[2];
    const float* Wm1      = (const float*)d_in[3];
    const float* bm1      = (const float*)d_in[4];
    const float* Wm_pi    = (const float*)d_in[5];
    const float* Wm_v     = (const float*)d_in[6];
    const float* Wt1      = (const float*)d_in[7];
    const float* Wt2      = (const float*)d_in[8];
    const float* W1       = (const float*)d_in[9];
    const float* b1       = (const float*)d_in[10];
    const float* Wpi      = (const float*)d_in[11];
    const float* Wv       = (const float*)d_in[12];
    float* out = (float*)d_out;

    cudaFuncSetAttribute(phaseA_fast,     cudaFuncAttributeMaxDynamicSharedMemorySize, SMEM_BYTES);
    cudaFuncSetAttribute(phaseA_fix_part, cudaFuncAttributeMaxDynamicSharedMemorySize, SMEM_BYTES);
    cudaFuncSetAttribute(phaseB_fast,     cudaFuncAttributeMaxDynamicSharedMemorySize, SMEM_BYTES);
    cudaFuncSetAttribute(phaseB_fix_part, cudaFuncAttributeMaxDynamicSharedMemorySize, SMEM_BYTES);

    convert_obs_kernel<<<(B_AG*DID)/(256*8), 256>>>(obs);
    dim3 gW(HID/32, DID/32, 10);
    convert_w_kernel<<<gW, dim3(32, 8)>>>(Wm1, Wt1, W1);

    phaseA_fast<<<B_AG/MT, NT, SMEM_BYTES>>>(
        dones, exec_opt, bm1, Wm_pi, Wm_v, Wt2, out);
    dim3 gAp(FIXA_CAP/MT, 16);
    phaseA_fix_part<<<gAp, NT, SMEM_BYTES>>>(bm1, Wm_pi, Wm_v, Wt2);
    phaseA_fix_final<<<FIXA_CAP/128, 128>>>(dones, exec_opt, out);

    compact_kernel<<<B_AG/128, 128>>>(exec_opt);

    dim3 gB(B_AG/MT, NOPT);
    phaseB_fast<<<gB, NT, SMEM_BYTES>>>(b1, Wpi, Wv, out);
    dim3 gBp(FIXB_CAP/MT, 8, NOPT);
    phaseB_fix_part<<<gBp, NT, SMEM_BYTES>>>(b1, Wpi, Wv);
    dim3 gBf(FIXB_CAP/128, NOPT);
    phaseB_fix_final<<<gBf, 128>>>(out);
}

// round 16
// speedup vs baseline: 2.2384x; 1.0125x over previous
#include <cuda_runtime.h>
#include <cuda_fp16.h>
#include <math.h>
#include <stdint.h>

#define B_AG 32768
#define DID  512
#define HID  1024
#define NOPT 8
#define NACT 16

#define MT    64
#define NTILE 128
#define KCH   32
#define NCH   (DID/KCH)
#define NT    128

#define TAU 4e-3f
#define FIXA_CAP 4096
#define FIXB_CAP 512

// ---- shared stage layout (all GEMM kernels) ----
#define A_HI 0
#define A_LO 5120
#define B_HI 10240
#define B_LO 20480
#define STAGE_BYTES 30720
#define ST_OFF(s)  (1024 + (s)*STAGE_BYTES)

// ---- fix-kernel layout (R15, scalar epilogue) ----
#define HST_OFFB 1024
#define HSTS 133
#define FIN_OFFB 35072
#define FINS 20
#define HWS  20
#define HW_OFFB   62464
#define BIAS_OFFB 72704
#define MISC_OFFB 73216
#define SMEM_FIX 73984

// ---- fast-kernel layout (R8, MMA head epilogue) ----
#define FH_HI  1024            // fp16 h plane, aliases stage area post-GEMM
#define FH_LO  18432
#define FHSTR  272
#define FHW_HI 62464           // fp16 head-weight planes (32 rows x 272B)
#define FHW_LO 71168
#define FFIN0  62464           // fp32 finals alias HW region (post last head_mma)
#define FFIN1  70912
#define FFINSTR 33
#define FBIAS  79872
#define FMISC  80384
#define SMEM_FAST 81152

__device__ int    g_opt_cnt[NOPT];
__device__ int    g_opt_list[NOPT*B_AG];
__device__ int    g_meta_act[B_AG];
__device__ int    g_term_dec[B_AG];
__device__ int    g_fixA_cnt;
__device__ int    g_fixA_list[FIXA_CAP];
__device__ int    g_fixB_cnt[NOPT];
__device__ int    g_fixB_list[NOPT*FIXB_CAP];
__device__ float  g_fixA_part[16][FIXA_CAP][17];
__device__ float  g_fixB_part[8][NOPT][FIXB_CAP][17];
__device__ __half g_obsHi[(size_t)B_AG*DID];
__device__ __half g_obsLo[(size_t)B_AG*DID];
__device__ __half g_wHiT[(size_t)10*HID*DID];   // K-major: [mat][h][k]
__device__ __half g_wLoT[(size_t)10*HID*DID];

// ---------------------------------------------------------------------------
__device__ __forceinline__ void cp16(uint32_t dst, const void* src) {
    asm volatile("cp.async.cg.shared.global [%0], [%1], 16;" :: "r"(dst), "l"(src));
}
#define CP_COMMIT() asm volatile("cp.async.commit_group;")

__device__ __forceinline__ void ldm4(uint32_t a, uint32_t r[4]) {
    asm volatile("ldmatrix.sync.aligned.m8n8.x4.shared.b16 {%0,%1,%2,%3}, [%4];"
        : "=r"(r[0]), "=r"(r[1]), "=r"(r[2]), "=r"(r[3]) : "r"(a));
}
__device__ __forceinline__ void mma16816(float d[4], const uint32_t a[4],
                                         uint32_t b0, uint32_t b1) {
    asm volatile("mma.sync.aligned.m16n8k16.row.col.f32.f16.f16.f32 "
        "{%0,%1,%2,%3}, {%4,%5,%6,%7}, {%8,%9}, {%0,%1,%2,%3};"
        : "+f"(d[0]), "+f"(d[1]), "+f"(d[2]), "+f"(d[3])
        : "r"(a[0]), "r"(a[1]), "r"(a[2]), "r"(a[3]), "r"(b0), "r"(b1));
}

// ---------------------------------------------------------------------------
__global__ void __launch_bounds__(256)
convert_obs_kernel(const float* __restrict__ obs) {
    size_t i = ((size_t)blockIdx.x*256 + threadIdx.x)*8;
    float v[8]; __half hi[8], lo[8];
    #pragma unroll
    for (int k = 0; k < 8; ++k) v[k] = obs[i + k];
    #pragma unroll
    for (int k = 0; k < 8; ++k) {
        hi[k] = __float2half_rn(v[k]);
        lo[k] = __float2half_rn(v[k] - __half2float(hi[k]));
    }
    *(uint4*)&g_obsHi[i] = *(uint4*)hi;
    *(uint4*)&g_obsLo[i] = *(uint4*)lo;
    if (blockIdx.x == 0 && threadIdx.x < NOPT) {
        g_opt_cnt[threadIdx.x] = 0;
        g_fixB_cnt[threadIdx.x] = 0;
        if (threadIdx.x == 0) g_fixA_cnt = 0;
    }
}

__global__ void __launch_bounds__(256)
convert_w_kernel(const float* __restrict__ Wm1,
                 const float* __restrict__ Wt1,
                 const float* __restrict__ W1) {
    __shared__ float tile[32][33];
    const int m = blockIdx.z;
    const float* src = (m == 0) ? Wm1 : (m == 1) ? Wt1 : W1 + (size_t)(m-2)*DID*HID;
    const int h0 = blockIdx.x * 32;
    const int k0 = blockIdx.y * 32;
    const int tx = threadIdx.x, ty0 = threadIdx.y;
    #pragma unroll
    for (int r = 0; r < 32; r += 8)
        tile[r + ty0][tx] = src[(size_t)(k0 + r + ty0)*HID + h0 + tx];
    __syncthreads();
    __half* dHi = g_wHiT + (size_t)m*HID*DID;
    __half* dLo = g_wLoT + (size_t)m*HID*DID;
    #pragma unroll
    for (int r = 0; r < 32; r += 8) {
        float x = tile[tx][r + ty0];
        __half hi = __float2half_rn(x);
        __half lo = __float2half_rn(x - __half2float(hi));
        size_t o = (size_t)(h0 + r + ty0)*DID + k0 + tx;
        dHi[o] = hi; dLo[o] = lo;
    }
}

// ---------------------------------------------------------------------------
// 3-pass GEMM tile (exact; fix path)
// ---------------------------------------------------------------------------
__device__ __forceinline__ void gemm3(uint32_t su, int t,
    const __half* aHi0, const __half* aHi1,
    const __half* aLo0, const __half* aLo1,
    const __half* bHi,  const __half* bLo,
    float acc[2][8][4])
{
    const int lane = t & 31, w = t >> 5;
    const int wm = (w & 1) * 32, wn = (w >> 1) * 64;
    const uint32_t drow = (uint32_t)((t >> 2)*80 + (t & 3)*16);

    #define FILL3(s, kc) do {                                   \
        uint32_t _b = su + ST_OFF(s) + drow;                    \
        const int _ko = (kc)*KCH;                               \
        cp16(_b + A_HI,        aHi0 + _ko);                     \
        cp16(_b + A_HI + 2560, aHi1 + _ko);                     \
        cp16(_b + A_LO,        aLo0 + _ko);                     \
        cp16(_b + A_LO + 2560, aLo1 + _ko);                     \
        _Pragma("unroll")                                       \
        for (int _i = 0; _i < 4; ++_i) {                        \
            cp16(_b + B_HI + _i*2560, bHi + _i*32*DID + _ko);   \
            cp16(_b + B_LO + _i*2560, bLo + _i*32*DID + _ko);   \
        }                                                       \
        CP_COMMIT();                                            \
    } while (0)

    FILL3(0, 0);

    #pragma unroll 1
    for (int kc = 0; kc < NCH; ++kc) {
        const int cur = kc & 1;
        if (kc + 1 < NCH) {
            FILL3(cur ^ 1, kc + 1);
            asm volatile("cp.async.wait_group 1;");
        } else {
            asm volatile("cp.async.wait_group 0;");
        }
        __syncthreads();

        const uint32_t sb = su + ST_OFF(cur);
        #pragma unroll
        for (int ks = 0; ks < 2; ++ks) {
            const uint32_t ko = ks*32 + (lane >> 4)*16;
            const uint32_t aadr = sb + A_HI + (uint32_t)((wm + (lane & 15))*80) + ko;
            uint32_t ah0[4], ah1[4], al0[4], al1[4];
            ldm4(aadr,          ah0);
            ldm4(aadr + 16*80,  ah1);
            ldm4(aadr + 5120,         al0);
            ldm4(aadr + 5120 + 16*80, al1);
            uint32_t bh[4][4], bl[4][4];
            #pragma unroll
            for (int j = 0; j < 4; ++j) {
                const uint32_t badr = sb + B_HI
                    + (uint32_t)((wn + j*16 + (lane & 15))*80) + ko;
                ldm4(badr,         bh[j]);
                ldm4(badr + 10240, bl[j]);
            }
            #pragma unroll
            for (int j = 0; j < 4; ++j) {
                mma16816(acc[0][2*j  ], ah0, bh[j][0], bh[j][2]);
                mma16816(acc[0][2*j+1], ah0, bh[j][1], bh[j][3]);
                mma16816(acc[1][2*j  ], ah1, bh[j][0], bh[j][2]);
                mma16816(acc[1][2*j+1], ah1, bh[j][1], bh[j][3]);
            }
            #pragma unroll
            for (int j = 0; j < 4; ++j) {
                mma16816(acc[0][2*j  ], ah0, bl[j][0], bl[j][2]);
                mma16816(acc[0][2*j+1], ah0, bl[j][1], bl[j][3]);
                mma16816(acc[1][2*j  ], ah1, bl[j][0], bl[j][2]);
                mma16816(acc[1][2*j+1], ah1, bl[j][1], bl[j][3]);
            }
            #pragma unroll
            for (int j = 0; j < 4; ++j) {
                mma16816(acc[0][2*j  ], al0, bh[j][0], bh[j][2]);
                mma16816(acc[0][2*j+1], al0, bh[j][1], bh[j][3]);
                mma16816(acc[1][2*j  ], al1, bh[j][0], bh[j][2]);
                mma16816(acc[1][2*j+1], al1, bh[j][1], bh[j][3]);
            }
        }
        __syncthreads();
    }
    #undef FILL3
}

// ---------------------------------------------------------------------------
// 1-pass GEMM tile (hi*hi only; fast path)
// ---------------------------------------------------------------------------
__device__ __forceinline__ void gemm1(uint32_t su, int t,
    const __half* aHi0, const __half* aHi1,
    const __half* bHi,
    float acc[2][8][4])
{
    const int lane = t & 31, w = t >> 5;
    const int wm = (w & 1) * 32, wn = (w >> 1) * 64;
    const uint32_t drow = (uint32_t)((t >> 2)*80 + (t & 3)*16);

    #define FILL1(s, kc) do {                                   \
        uint32_t _b = su + ST_OFF(s) + drow;                    \
        const int _ko = (kc)*KCH;                               \
        cp16(_b + A_HI,        aHi0 + _ko);                     \
        cp16(_b + A_HI + 2560, aHi1 + _ko);                     \
        _Pragma("unroll")                                       \
        for (int _i = 0; _i < 4; ++_i)                          \
            cp16(_b + B_HI + _i*2560, bHi + _i*32*DID + _ko);   \
        CP_COMMIT();                                            \
    } while (0)

    FILL1(0, 0);

    #pragma unroll 1
    for (int kc = 0; kc < NCH; ++kc) {
        const int cur = kc & 1;
        if (kc + 1 < NCH) {
            FILL1(cur ^ 1, kc + 1);
            asm volatile("cp.async.wait_group 1;");
        } else {
            asm volatile("cp.async.wait_group 0;");
        }
        __syncthreads();

        const uint32_t sb = su + ST_OFF(cur);
        #pragma unroll
        for (int ks = 0; ks < 2; ++ks) {
            const uint32_t ko = ks*32 + (lane >> 4)*16;
            const uint32_t aadr = sb + A_HI + (uint32_t)((wm + (lane & 15))*80) + ko;
            uint32_t ah0[4], ah1[4];
            ldm4(aadr,          ah0);
            ldm4(aadr + 16*80,  ah1);
            uint32_t bh[4][4];
            #pragma unroll
            for (int j = 0; j < 4; ++j) {
                const uint32_t badr = sb + B_HI
                    + (uint32_t)((wn + j*16 + (lane & 15))*80) + ko;
                ldm4(badr, bh[j]);
            }
            #pragma unroll
            for (int j = 0; j < 4; ++j) {
                mma16816(acc[0][2*j  ], ah0, bh[j][0], bh[j][2]);
                mma16816(acc[0][2*j+1], ah0, bh[j][1], bh[j][3]);
                mma16816(acc[1][2*j  ], ah1, bh[j][0], bh[j][2]);
                mma16816(acc[1][2*j+1], ah1, bh[j][1], bh[j][3]);
            }
        }
        __syncthreads();
    }
    #undef FILL1
}

#define ZERO_ACC8(acc) do {                                \
    _Pragma("unroll") for (int _i = 0; _i < 2; ++_i)       \
    _Pragma("unroll") for (int _j = 0; _j < 8; ++_j)       \
    _Pragma("unroll") for (int _e = 0; _e < 4; ++_e)       \
        (acc)[_i][_j][_e] = 0.f;                           \
} while (0)

// ===========================================================================
// FAST-path head epilogue (R8 machinery): fp16 hi/lo H planes + head MMA
// ===========================================================================
__device__ __forceinline__ void f_stage_h(char* base, const float acc[2][8][4],
                                          int t) {
    const int lane = t & 31, w = t >> 5;
    const int wm = (w & 1) * 32, wn = (w >> 1) * 64;
    const float* bias_s = (const float*)(base + FBIAS);
    #pragma unroll
    for (int im = 0; im < 2; ++im) {
        #pragma unroll
        for (int j = 0; j < 8; ++j) {
            #pragma unroll
            for (int ep = 0; ep < 2; ++ep) {
                int row = wm + im*16 + (lane >> 2) + ep*8;
                int col = wn + j*8 + 2*(lane & 3);
                float x0 = fmaxf(acc[im][j][2*ep]   + bias_s[col],     0.f);
                float x1 = fmaxf(acc[im][j][2*ep+1] + bias_s[col + 1], 0.f);
                __half h0 = __float2half_rn(x0);
                __half h1 = __float2half_rn(x1);
                __half l0 = __float2half_rn(x0 - __half2float(h0));
                __half l1 = __float2half_rn(x1 - __half2float(h1));
                *(__half2*)(base + FH_HI + row*FHSTR + col*2) = __halves2half2(h0, h1);
                *(__half2*)(base + FH_LO + row*FHSTR + col*2) = __halves2half2(l0, l1);
            }
        }
    }
}

// head-GEMM h[64x128] @ headW^T[128x32], 3-pass hi/lo; warp w: n8 slice.
__device__ __forceinline__ void f_head_mma(uint32_t su, int t, float hacc[4][4]) {
    const int lane = t & 31, w = t >> 5;
    const uint32_t arow = su + FH_HI + (uint32_t)((lane & 15)*FHSTR) + (lane >> 4)*16;
    const uint32_t brow = su + FHW_HI
        + (uint32_t)(((w >> 1)*16 + (lane & 15))*FHSTR) + (lane >> 4)*16;
    const int sel = w & 1;
    #pragma unroll
    for (int k16 = 0; k16 < 8; ++k16) {
        const uint32_t ko = k16*32;
        uint32_t bh[4], bl[4];
        ldm4(brow + ko, bh);
        ldm4(brow + ko + (FHW_LO - FHW_HI), bl);
        const uint32_t b0h = sel ? bh[1] : bh[0], b1h = sel ? bh[3] : bh[2];
        const uint32_t b0l = sel ? bl[1] : bl[0], b1l = sel ? bl[3] : bl[2];
        #pragma unroll
        for (int m = 0; m < 4; ++m) {
            uint32_t ah[4], al[4];
            ldm4(arow + m*16*FHSTR + ko, ah);
            ldm4(arow + m*16*FHSTR + ko + (FH_LO - FH_HI), al);
            mma16816(hacc[m], ah, b0h, b1h);
            mma16816(hacc[m], ah, b0l, b1l);
            mma16816(hacc[m], al, b0h, b1h);
        }
    }
}

__device__ __forceinline__ void f_store_hacc(float* fin, int t,
                                             const float hacc[4][4]) {
    const int lane = t & 31, w = t >> 5;
    const int n0 = (w >> 1)*16 + (w & 1)*8;
    #pragma unroll
    for (int m = 0; m < 4; ++m) {
        #pragma unroll
        for (int e = 0; e < 4; ++e) {
            int row = m*16 + (lane >> 2) + 8*(e >> 1);
            int col = n0 + 2*(lane & 3) + (e & 1);
            fin[row*FFINSTR + col] = hacc[m][e];
        }
    }
}

__device__ __forceinline__ void f_zero_hw_tail(char* base, int t) {
    for (int i = t; i < 15*68; i += NT) {
        int row = 17 + i/68, wd = i % 68;
        *(uint32_t*)(base + FHW_HI + row*FHSTR + wd*4) = 0u;
        *(uint32_t*)(base + FHW_LO + row*FHSTR + wd*4) = 0u;
    }
}
__device__ __forceinline__ void f_put_hw(char* base, int o, int t, float v) {
    __half hi = __float2half_rn(v);
    __half lo = __float2half_rn(v - __half2float(hi));
    *(__half*)(base + FHW_HI + o*FHSTR + t*2) = hi;
    *(__half*)(base + FHW_LO + o*FHSTR + t*2) = lo;
}

// ===========================================================================
// Decision helpers (with flagging)
// ===========================================================================
__device__ __forceinline__ void finishA(int g, const float tot[17],
    const int* dones, const int* exec_opt, float* out, bool allow_flag)
{
    float m = tot[0], m2 = -1e30f; int am = 0;
    #pragma unroll
    for (int o = 1; o < 8; ++o) {
        if (tot[o] > m) { m2 = m; m = tot[o]; am = o; }
        else if (tot[o] > m2) m2 = tot[o];
    }
    float s = 0.f;
    #pragma unroll
    for (int o = 0; o < 8; ++o) s += expf(tot[o] - m);
    float lp = -logf(s);
    int eo = exec_opt[g];
    float tl = tot[9 + eo];
    float tp = 1.0f/(1.0f + expf(-tl));
    bool dn = (dones[g] != 0);
    bool term = dn || (tp > 0.5f);
    out[3*B_AG + g] = (float)am;
    out[4*B_AG + g] = tot[8];
    out[5*B_AG + g] = lp;
    out[6*B_AG + g] = tp;
    g_meta_act[g] = am;
    g_term_dec[g] = term ? 1 : 0;
    if (allow_flag) {
        bool f = ((m - m2) < TAU) || (!dn && (fabsf(tl) < TAU));
        if (f) {
            int p = atomicAdd(&g_fixA_cnt, 1);
            if (p < FIXA_CAP) g_fixA_list[p] = g;
        }
    }
}

__device__ __forceinline__ void finishB(int g, int opt, const float lg17[17],
                                        float* out, bool allow_flag) {
    float m = lg17[0], m2 = -1e30f; int am = 0;
    #pragma unroll
    for (int a = 1; a < NACT; ++a) {
        if (lg17[a] > m) { m2 = m; m = lg17[a]; am = a; }
        else if (lg17[a] > m2) m2 = lg17[a];
    }
    float s = 0.f;
    #pragma unroll
    for (int a = 0; a < NACT; ++a) s += expf(lg17[a] - m);
    float lp = -logf(s);
    out[          g] = (float)am;
    out[  B_AG +  g] = lg17[16];
    out[2*B_AG +  g] = lp;
    if (allow_flag && (m - m2) < TAU) {
        int p = atomicAdd(&g_fixB_cnt[opt], 1);
        if (p < FIXB_CAP) g_fixB_list[opt*FIXB_CAP + p] = g;
    }
}

// ===========================================================================
// FAST kernels
// ===========================================================================
__global__ void __launch_bounds__(NT, 2)
phaseA_fast(const int*   __restrict__ dones,
            const int*   __restrict__ exec_opt,
            const float* __restrict__ bm1,
            const float* __restrict__ Wm_pi,
            const float* __restrict__ Wm_v,
            const float* __restrict__ Wt2,
            float* __restrict__ out)
{
    extern __shared__ float smf[];
    char* base = (char*)smf;
    const uint32_t su = (uint32_t)__cvta_generic_to_shared(smf);
    const int t = threadIdx.x;
    const int g0 = blockIdx.x * MT;

    f_zero_hw_tail(base, t);

    const size_t arow = (size_t)(g0 + (t >> 2))*DID + (t & 3)*8;
    const __half* aHi0 = g_obsHi + arow;
    const __half* aHi1 = aHi0 + (size_t)32*DID;

    float hacc0[4][4], hacc1[4][4];
    #pragma unroll
    for (int m = 0; m < 4; ++m)
        #pragma unroll
        for (int e = 0; e < 4; ++e) { hacc0[m][e] = 0.f; hacc1[m][e] = 0.f; }

    #pragma unroll 1
    for (int net = 0; net < 2; ++net) {
        #pragma unroll 1
        for (int ht = 0; ht < HID/NTILE; ++ht) {
            const int hbase = ht * NTILE;
            // head weights + bias -> fp16 hi/lo planes (col = t)
            if (net == 0) {
                ((float*)(base + FBIAS))[t] = bm1[hbase + t];
                const float* wp = Wm_pi + (size_t)(hbase + t)*NOPT;
                #pragma unroll
                for (int o = 0; o < 8; ++o) f_put_hw(base, o, t, wp[o]);
                f_put_hw(base, 8, t, Wm_v[hbase + t]);
                #pragma unroll
                for (int o = 9; o < 17; ++o) f_put_hw(base, o, t, 0.f);
            } else {
                ((float*)(base + FBIAS))[t] = 0.f;
                const float* wp = Wt2 + (size_t)(hbase + t)*NOPT;
                #pragma unroll
                for (int o = 0; o < 8; ++o) f_put_hw(base, o, t, wp[o]);
                #pragma unroll
                for (int o = 8; o < 17; ++o) f_put_hw(base, o, t, 0.f);
            }
            const size_t brow = ((size_t)net*HID + hbase + (t >> 2))*DID + (t & 3)*8;

            float acc[2][8][4];
            ZERO_ACC8(acc);
            gemm1(su, t, aHi0, aHi1, g_wHiT + brow, acc);
            f_stage_h(base, acc, t);
            __syncthreads();
            f_head_mma(su, t, net == 0 ? hacc0 : hacc1);
            __syncthreads();
        }
    }

    f_store_hacc((float*)(base + FFIN0), t, hacc0);
    f_store_hacc((float*)(base + FFIN1), t, hacc1);
    __syncthreads();

    if (t < MT) {
        const float* fin0 = (const float*)(base + FFIN0) + t*FFINSTR;
        const float* fin1 = (const float*)(base + FFIN1) + t*FFINSTR;
        float tot[17];
        #pragma unroll
        for (int k = 0; k < 9; ++k) tot[k] = fin0[k];
        #pragma unroll
        for (int k = 0; k < 8; ++k) tot[9 + k] = fin1[k];
        finishA(g0 + t, tot, dones, exec_opt, out, true);
    }
}

__global__ void __launch_bounds__(NT, 2)
phaseB_fast(const float* __restrict__ b1, const float* __restrict__ Wpi,
            const float* __restrict__ Wv, float* __restrict__ out)
{
    const int opt   = blockIdx.y;
    const int start = blockIdx.x * MT;
    const int cnt   = g_opt_cnt[opt];
    if (start >= cnt) return;
    const int nvalid = min(MT, cnt - start);

    extern __shared__ float smf[];
    char* base = (char*)smf;
    const uint32_t su = (uint32_t)__cvta_generic_to_shared(smf);
    const int t = threadIdx.x;
    int* idx_s = (int*)(base + FMISC);

    f_zero_hw_tail(base, t);

    if (t < MT) {
        int src = opt*B_AG + start + ((t < nvalid) ? t : 0);
        idx_s[t] = g_opt_list[src];
    }
    __syncthreads();

    const size_t arow0 = (size_t)idx_s[t >> 2]*DID + (t & 3)*8;
    const size_t arow1 = (size_t)idx_s[(t >> 2) + 32]*DID + (t & 3)*8;
    const __half* aHi0 = g_obsHi + arow0;
    const __half* aHi1 = g_obsHi + arow1;

    const float* bg   = b1  + (size_t)opt*HID;
    const float* wpig = Wpi + (size_t)opt*HID*NACT;
    const float* wvg  = Wv  + (size_t)opt*HID;

    float hacc[4][4];
    #pragma unroll
    for (int m = 0; m < 4; ++m)
        #pragma unroll
        for (int e = 0; e < 4; ++e) hacc[m][e] = 0.f;

    #pragma unroll 1
    for (int ht = 0; ht < HID/NTILE; ++ht) {
        const int hbase = ht * NTILE;
        ((float*)(base + FBIAS))[t] = bg[hbase + t];
        {
            const float* wp = wpig + (size_t)(hbase + t)*NACT;
            #pragma unroll
            for (int a = 0; a < NACT; ++a) f_put_hw(base, a, t, wp[a]);
            f_put_hw(base, 16, t, wvg[hbase + t]);
        }
        const size_t brow = ((size_t)(2 + opt)*HID + hbase + (t >> 2))*DID + (t & 3)*8;

        float acc[2][8][4];
        ZERO_ACC8(acc);
        gemm1(su, t, aHi0, aHi1, g_wHiT + brow, acc);
        f_stage_h(base, acc, t);
        __syncthreads();
        f_head_mma(su, t, hacc);
        __syncthreads();
    }

    f_store_hacc((float*)(base + FFIN0), t, hacc);
    __syncthreads();

    if (t < nvalid) {
        const float* fin = (const float*)(base + FFIN0) + t*FFINSTR;
        float lg17[17];
        #pragma unroll
        for (int k = 0; k < 17; ++k) lg17[k] = fin[k];
        finishB(idx_s[t], opt, lg17, out, true);
    }
}

// ===========================================================================
// FIX path (R15, scalar epilogue; unchanged)
// ===========================================================================
__device__ __forceinline__ void x_stage_h(float* smf, const float acc[2][8][4],
                                          int t) {
    const int lane = t & 31, w = t >> 5;
    const int wm = (w & 1) * 32, wn = (w >> 1) * 64;
    float* hst = smf + HST_OFFB/4;
    const float* bias_s = smf + BIAS_OFFB/4;
    #pragma unroll
    for (int im = 0; im < 2; ++im) {
        #pragma unroll
        for (int j = 0; j < 8; ++j) {
            #pragma unroll
            for (int e = 0; e < 4; ++e) {
                int row = wm + im*16 + (lane >> 2) + (e >> 1)*8;
                int col = wn + j*8 + 2*(lane & 3) + (e & 1);
                float h = acc[im][j][e] + bias_s[col];
                hst[row*HSTS + col] = fmaxf(h, 0.f);
            }
        }
    }
}

__device__ __forceinline__ void x_loadA_heads(float* smf, int t, int net, int hbase,
    const float* bm1, const float* Wm_pi, const float* Wm_v, const float* Wt2)
{
    float* hw     = smf + HW_OFFB/4;
    float* bias_s = smf + BIAS_OFFB/4;
    if (net == 0) {
        const float* wp = Wm_pi + (size_t)(hbase + t)*NOPT;
        #pragma unroll
        for (int o = 0; o < NOPT; ++o) hw[t*HWS + o] = wp[o];
        hw[t*HWS + 8] = Wm_v[hbase + t];
        bias_s[t] = bm1[hbase + t];
    } else {
        const float* wp = Wt2 + (size_t)(hbase + t)*NOPT;
        #pragma unroll
        for (int o = 0; o < NOPT; ++o) hw[t*HWS + o] = wp[o];
        bias_s[t] = 0.f;
    }
}

__device__ __forceinline__ void x_headA_accum(const float* smf, int t, int net,
                                              float accM[9], float accT[8]) {
    const float* hst = smf + HST_OFFB/4;
    const float* hw  = smf + HW_OFFB/4;
    const int r = t & 63, cbase = (t >> 6)*64;
    if (net == 0) {
        #pragma unroll 4
        for (int c = 0; c < 64; ++c) {
            float h = hst[r*HSTS + cbase + c];
            const float* hwc = hw + (cbase + c)*HWS;
            float4 w0 = *(const float4*)(hwc);
            float4 w1 = *(const float4*)(hwc + 4);
            accM[0] += h*w0.x; accM[1] += h*w0.y;
            accM[2] += h*w0.z; accM[3] += h*w0.w;
            accM[4] += h*w1.x; accM[5] += h*w1.y;
            accM[6] += h*w1.z; accM[7] += h*w1.w;
            accM[8] += h*hwc[8];
        }
    } else {
        #pragma unroll 4
        for (int c = 0; c < 64; ++c) {
            float h = hst[r*HSTS + cbase + c];
            const float* hwc = hw + (cbase + c)*HWS;
            float4 w0 = *(const float4*)(hwc);
            float4 w1 = *(const float4*)(hwc + 4);
            accT[0] += h*w0.x; accT[1] += h*w0.y;
            accT[2] += h*w0.z; accT[3] += h*w0.w;
            accT[4] += h*w1.x; accT[5] += h*w1.y;
            accT[6] += h*w1.z; accT[7] += h*w1.w;
        }
    }
}

__global__ void __launch_bounds__(NT, 2)
phaseA_fix_part(const float* __restrict__ bm1,
                const float* __restrict__ Wm_pi,
                const float* __restrict__ Wm_v,
                const float* __restrict__ Wt2)
{
    const int cnt = min(g_fixA_cnt, FIXA_CAP);
    const int start = blockIdx.x * MT;
    if (start >= cnt) return;
    const int nvalid = min(MT, cnt - start);
    const int tt = blockIdx.y;
    const int net = tt >> 3, hbase = (tt & 7)*NTILE;

    extern __shared__ float smf[];
    const uint32_t su = (uint32_t)__cvta_generic_to_shared(smf);
    const int t = threadIdx.x;
    float* fin = smf + FIN_OFFB/4;
    int* idx_s = (int*)(smf + MISC_OFFB/4);

    if (t < MT) idx_s[t] = g_fixA_list[start + ((t < nvalid) ? t : 0)];
    __syncthreads();

    const size_t arow0 = (size_t)idx_s[t >> 2]*DID + (t & 3)*8;
    const size_t arow1 = (size_t)idx_s[(t >> 2) + 32]*DID + (t & 3)*8;

    x_loadA_heads(smf, t, net, hbase, bm1, Wm_pi, Wm_v, Wt2);
    const size_t brow = ((size_t)net*HID + hbase + (t >> 2))*DID + (t & 3)*8;

    float acc[2][8][4];
    ZERO_ACC8(acc);
    gemm3(su, t, g_obsHi + arow0, g_obsHi + arow1,
          g_obsLo + arow0, g_obsLo + arow1,
          g_wHiT + brow, g_wLoT + brow, acc);
    x_stage_h(smf, acc, t);
    __syncthreads();

    float accM[9], accT[8];
    #pragma unroll
    for (int k = 0; k < 9; ++k) accM[k] = 0.f;
    #pragma unroll
    for (int k = 0; k < 8; ++k) accT[k] = 0.f;
    x_headA_accum(smf, t, net, accM, accT);
    __syncthreads();

    const int r = t & 63;
    if (t >= 64) {
        #pragma unroll
        for (int k = 0; k < 9; ++k) fin[r*FINS + k] = accM[k];
        #pragma unroll
        for (int k = 0; k < 8; ++k) fin[r*FINS + 9 + k] = accT[k];
    }
    __syncthreads();

    if (t < nvalid) {
        float* dst = g_fixA_part[tt][start + t];
        if (net == 0) {
            #pragma unroll
            for (int k = 0; k < 9; ++k) dst[k] = accM[k] + fin[t*FINS + k];
        } else {
            #pragma unroll
            for (int k = 0; k < 8; ++k) dst[9 + k] = accT[k] + fin[t*FINS + 9 + k];
        }
    }
}

__global__ void __launch_bounds__(128)
phaseA_fix_final(const int* __restrict__ dones,
                 const int* __restrict__ exec_opt,
                 float* __restrict__ out)
{
    const int cnt = min(g_fixA_cnt, FIXA_CAP);
    const int s = blockIdx.x*128 + threadIdx.x;
    if (s >= cnt) return;
    float tot[17];
    #pragma unroll
    for (int k = 0; k < 17; ++k) tot[k] = 0.f;
    #pragma unroll
    for (int tile = 0; tile < 8; ++tile) {
        const float* p = g_fixA_part[tile][s];
        #pragma unroll
        for (int k = 0; k < 9; ++k) tot[k] += p[k];
    }
    #pragma unroll
    for (int tile = 8; tile < 16; ++tile) {
        const float* p = g_fixA_part[tile][s];
        #pragma unroll
        for (int k = 0; k < 8; ++k) tot[9 + k] += p[9 + k];
    }
    finishA(g_fixA_list[s], tot, dones, exec_opt, out, false);
}

__global__ void __launch_bounds__(128)
compact_kernel(const int* __restrict__ exec_opt) {
    __shared__ int s_cnt[NOPT], s_base[NOPT];
    const int t = threadIdx.x;
    const int g = blockIdx.x*128 + t;
    if (t < NOPT) s_cnt[t] = 0;
    __syncthreads();
    const int myno = g_term_dec[g] ? g_meta_act[g] : exec_opt[g];
    const int pos = atomicAdd(&s_cnt[myno], 1);
    __syncthreads();
    if (t < NOPT) s_base[t] = atomicAdd(&g_opt_cnt[t], s_cnt[t]);
    __syncthreads();
    g_opt_list[myno*B_AG + s_base[myno] + pos] = g;
}

__device__ __forceinline__ void x_loadB_heads(float* smf, int t, int hbase,
    const float* bg, const float* wpig, const float* wvg)
{
    float* hw     = smf + HW_OFFB/4;
    float* bias_s = smf + BIAS_OFFB/4;
    const float* wp = wpig + (size_t)(hbase + t)*NACT;
    #pragma unroll
    for (int a = 0; a < NACT; ++a) hw[t*HWS + a] = wp[a];
    hw[t*HWS + 16] = wvg[hbase + t];
    bias_s[t] = bg[hbase + t];
}

__device__ __forceinline__ void x_headB_accum(const float* smf, int t,
                                              float accB[17]) {
    const float* hst = smf + HST_OFFB/4;
    const float* hw  = smf + HW_OFFB/4;
    const int r = t & 63, cbase = (t >> 6)*64;
    #pragma unroll 2
    for (int c = 0; c < 64; ++c) {
        float h = hst[r*HSTS + cbase + c];
        const float* hwc = hw + (cbase + c)*HWS;
        float4 w0 = *(const float4*)(hwc);
        float4 w1 = *(const float4*)(hwc + 4);
        float4 w2 = *(const float4*)(hwc + 8);
        float4 w3 = *(const float4*)(hwc + 12);
        accB[0]  += h*w0.x; accB[1]  += h*w0.y;
        accB[2]  += h*w0.z; accB[3]  += h*w0.w;
        accB[4]  += h*w1.x; accB[5]  += h*w1.y;
        accB[6]  += h*w1.z; accB[7]  += h*w1.w;
        accB[8]  += h*w2.x; accB[9]  += h*w2.y;
        accB[10] += h*w2.z; accB[11] += h*w2.w;
        accB[12] += h*w3.x; accB[13] += h*w3.y;
        accB[14] += h*w3.z; accB[15] += h*w3.w;
        accB[16] += h*hwc[16];
    }
}

__global__ void __launch_bounds__(NT, 2)
phaseB_fix_part(const float* __restrict__ b1, const float* __restrict__ Wpi,
                const float* __restrict__ Wv)
{
    const int opt = blockIdx.z;
    const int cnt = min(g_fixB_cnt[opt], FIXB_CAP);
    const int start = blockIdx.x * MT;
    if (start >= cnt) return;
    const int nvalid = min(MT, cnt - start);
    const int ht = blockIdx.y, hbase = ht*NTILE;

    extern __shared__ float smf[];
    const uint32_t su = (uint32_t)__cvta_generic_to_shared(smf);
    const int t = threadIdx.x;
    float* fin = smf + FIN_OFFB/4;
    int* idx_s = (int*)(smf + MISC_OFFB/4);

    if (t < MT)
        idx_s[t] = g_fixB_list[opt*FIXB_CAP + start + ((t < nvalid) ? t : 0)];
    __syncthreads();

    const size_t arow0 = (size_t)idx_s[t >> 2]*DID + (t & 3)*8;
    const size_t arow1 = (size_t)idx_s[(t >> 2) + 32]*DID + (t & 3)*8;

    const float* bg   = b1  + (size_t)opt*HID;
    const float* wpig = Wpi + (size_t)opt*HID*NACT;
    const float* wvg  = Wv  + (size_t)opt*HID;

    x_loadB_heads(smf, t, hbase, bg, wpig, wvg);
    const size_t brow = ((size_t)(2 + opt)*HID + hbase + (t >> 2))*DID + (t & 3)*8;

    float acc[2][8][4];
    ZERO_ACC8(acc);
    gemm3(su, t, g_obsHi + arow0, g_obsHi + arow1,
          g_obsLo + arow0, g_obsLo + arow1,
          g_wHiT + brow, g_wLoT + brow, acc);
    x_stage_h(smf, acc, t);
    __syncthreads();

    float accB[17];
    #pragma unroll
    for (int k = 0; k < 17; ++k) accB[k] = 0.f;
    x_headB_accum(smf, t, accB);
    __syncthreads();

    const int r = t & 63;
    if (t >= 64) {
        #pragma unroll
        for (int k = 0; k < 17; ++k) fin[r*FINS + k] = accB[k];
    }
    __syncthreads();

    if (t < nvalid) {
        float* dst = g_fixB_part[ht][opt][start + t];
        #pragma unroll
        for (int k = 0; k < 17; ++k) dst[k] = accB[k] + fin[t*FINS + k];
    }
}

__global__ void __launch_bounds__(128)
phaseB_fix_final(float* __restrict__ out)
{
    const int opt = blockIdx.y;
    const int cnt = min(g_fixB_cnt[opt], FIXB_CAP);
    const int s = blockIdx.x*128 + threadIdx.x;
    if (s >= cnt) return;
    float lg17[17];
    #pragma unroll
    for (int k = 0; k < 17; ++k) lg17[k] = 0.f;
    #pragma unroll
    for (int tile = 0; tile < 8; ++tile) {
        const float* p = g_fixB_part[tile][opt][s];
        #pragma unroll
        for (int k = 0; k < 17; ++k) lg17[k] += p[k];
    }
    finishB(g_fixB_list[opt*FIXB_CAP + s], opt, lg17, out, false);
}

extern "C" void kernel_launch(void* const* d_in, const int* in_sizes, int n_in,
                              void* d_out, int out_size) {
    const float* obs      = (const float*)d_in[0];
    const int*   dones    = (const int*)  d_in[1];
    const int*   exec_opt = (const int*)  d_in[2];
    const float* Wm1      = (const float*)d_in[3];
    const float* bm1      = (const float*)d_in[4];
    const float* Wm_pi    = (const float*)d_in[5];
    const float* Wm_v     = (const float*)d_in[6];
    const float* Wt1      = (const float*)d_in[7];
    const float* Wt2      = (const float*)d_in[8];
    const float* W1       = (const float*)d_in[9];
    const float* b1       = (const float*)d_in[10];
    const float* Wpi      = (const float*)d_in[11];
    const float* Wv       = (const float*)d_in[12];
    float* out = (float*)d_out;

    cudaFuncSetAttribute(phaseA_fast,     cudaFuncAttributeMaxDynamicSharedMemorySize, SMEM_FAST);
    cudaFuncSetAttribute(phaseB_fast,     cudaFuncAttributeMaxDynamicSharedMemorySize, SMEM_FAST);
    cudaFuncSetAttribute(phaseA_fix_part, cudaFuncAttributeMaxDynamicSharedMemorySize, SMEM_FIX);
    cudaFuncSetAttribute(phaseB_fix_part, cudaFuncAttributeMaxDynamicSharedMemorySize, SMEM_FIX);

    convert_obs_kernel<<<(B_AG*DID)/(256*8), 256>>>(obs);
    dim3 gW(HID/32, DID/32, 10);
    convert_w_kernel<<<gW, dim3(32, 8)>>>(Wm1, Wt1, W1);

    phaseA_fast<<<B_AG/MT, NT, SMEM_FAST>>>(
        dones, exec_opt, bm1, Wm_pi, Wm_v, Wt2, out);
    dim3 gAp(FIXA_CAP/MT, 16);
    phaseA_fix_part<<<gAp, NT, SMEM_FIX>>>(bm1, Wm_pi, Wm_v, Wt2);
    phaseA_fix_final<<<FIXA_CAP/128, 128>>>(dones, exec_opt, out);

    compact_kernel<<<B_AG/128, 128>>>(exec_opt);

    dim3 gB(B_AG/MT, NOPT);
    phaseB_fast<<<gB, NT, SMEM_FAST>>>(b1, Wpi, Wv, out);
    dim3 gBp(FIXB_CAP/MT, 8, NOPT);
    phaseB_fix_part<<<gBp, NT, SMEM_FIX>>>(b1, Wpi, Wv);
    dim3 gBf(FIXB_CAP/128, NOPT);
    phaseB_fix_final<<<gBf, 128>>>(out);
}